// round 5
// baseline (speedup 1.0000x reference)
#include <cuda_runtime.h>
#include <cstdint>
#include <cstddef>

#define BATCH 4
#define SEQ 2048
#define DMODEL 384
#define NHEADS 6
#define HD 64
#define BH (BATCH*NHEADS)      /* 24 */
#define NROWS (BH*SEQ)         /* 49152 */

// ---------------- scratch (static device allocations; no cudaMalloc allowed) ----
__device__ int8_t g_Q  [(size_t)BH*SEQ*HD];       // [b][h][n][d] int8
__device__ int8_t g_K  [(size_t)BH*SEQ*HD];       // [b][h][n][d] int8
__device__ int8_t g_Vt [(size_t)BH*HD*SEQ];       // [b][h][d][n] int8 (transposed for AV dp4a)
__device__ int8_t g_S  [(size_t)BH*SEQ*SEQ];      // logits int8, then attn uint8 in-place (100MB)
__device__ int8_t g_ctx[(size_t)BATCH*SEQ*DMODEL];// [b][n][h*hd] int8
__device__ int    g_rmax[NROWS];
__device__ int    g_rinv[NROWS];

__device__ __forceinline__ int dp4a_us(unsigned a, int b, int c) {
    int d;
    asm("dp4a.u32.s32 %0, %1, %2, %3;" : "=r"(d) : "r"(a), "r"(b), "r"(c));
    return d;
}

__device__ __forceinline__ int clamp_i8(int v) {
    return v < -128 ? -128 : (v > 127 ? 127 : v);
}

// ---------------------------------------------------------------------------
// Kernel 1: QKV projection.  Y = requantize(x @ W^T + b, 16384, 8) -> int8
// grid (8192/64, 384/64, 3), block 256 (16x16 threads, 4x4 micro-tile)
// ---------------------------------------------------------------------------
__global__ void proj_kernel(const float* __restrict__ x,
                            const float* __restrict__ wq, const float* __restrict__ bq,
                            const float* __restrict__ wk, const float* __restrict__ bk,
                            const float* __restrict__ wv, const float* __restrict__ bv)
{
    __shared__ float xs[64][17];
    __shared__ float ws[64][17];

    const int z  = blockIdx.z;
    const float* w    = (z == 0) ? wq : ((z == 1) ? wk : wv);
    const float* bias = (z == 0) ? bq : ((z == 1) ? bk : bv);

    const int m0 = blockIdx.x * 64;
    const int n0 = blockIdx.y * 64;
    const int tid = threadIdx.x;
    const int tx = tid & 15;
    const int ty = tid >> 4;

    float acc[4][4] = {};

    for (int k0 = 0; k0 < DMODEL; k0 += 16) {
        #pragma unroll
        for (int i = 0; i < 4; i++) {
            int idx = tid + i * 256;
            int r = idx >> 4, c = idx & 15;
            xs[r][c] = x[(size_t)(m0 + r) * DMODEL + k0 + c];
            ws[r][c] = w[(size_t)(n0 + r) * DMODEL + k0 + c];
        }
        __syncthreads();
        #pragma unroll
        for (int kk = 0; kk < 16; kk++) {
            float a[4], b[4];
            #pragma unroll
            for (int i = 0; i < 4; i++) a[i] = xs[ty * 4 + i][kk];
            #pragma unroll
            for (int j = 0; j < 4; j++) b[j] = ws[tx * 4 + j][kk];
            #pragma unroll
            for (int i = 0; i < 4; i++)
                #pragma unroll
                for (int j = 0; j < 4; j++)
                    acc[i][j] += a[i] * b[j];
        }
        __syncthreads();
    }

    #pragma unroll
    for (int i = 0; i < 4; i++) {
        int m = m0 + ty * 4 + i;
        int b = m >> 11;          // batch
        int n = m & 2047;         // seq pos
        #pragma unroll
        for (int j = 0; j < 4; j++) {
            int c = n0 + tx * 4 + j;
            int h = c >> 6;
            int d = c & 63;
            float v = acc[i][j] + bias[c];
            // requantize(v, 16384, 8) replicating reference rounding order:
            float r = v * 16384.0f;
            r = r * (1.0f / 256.0f);       // exact power-of-2 division
            r = floorf(r);
            r = fminf(fmaxf(r, -128.0f), 127.0f);
            int8_t q = (int8_t)(int)r;
            if (z == 2) {
                g_Vt[((size_t)(b * NHEADS + h) * HD + d) * SEQ + n] = q;
            } else if (z == 0) {
                g_Q[((size_t)(b * NHEADS + h) * SEQ + n) * HD + d] = q;
            } else {
                g_K[((size_t)(b * NHEADS + h) * SEQ + n) * HD + d] = q;
            }
        }
    }
}

// ---------------------------------------------------------------------------
// Kernel 2: logits = requantize(Q @ K^T, 5, 12) -> int8 (exact integer math)
// grid (2048/64 k-tiles, 2048/64 q-tiles, 24), block 256
// ---------------------------------------------------------------------------
__global__ void logits_kernel()
{
    __shared__ int qs[64][17];
    __shared__ int ks[64][17];

    const int bh = blockIdx.z;
    const int k0t = blockIdx.x * 64;
    const int q0t = blockIdx.y * 64;
    const int tid = threadIdx.x;
    const int tx = tid & 15;
    const int ty = tid >> 4;

    const int* Qw = (const int*)g_Q + (size_t)bh * SEQ * (HD / 4);
    const int* Kw = (const int*)g_K + (size_t)bh * SEQ * (HD / 4);

    #pragma unroll
    for (int i = 0; i < 4; i++) {
        int idx = tid + i * 256;
        int r = idx >> 4, c = idx & 15;
        qs[r][c] = Qw[(size_t)(q0t + r) * 16 + c];
        ks[r][c] = Kw[(size_t)(k0t + r) * 16 + c];
    }
    __syncthreads();

    int acc[4][4] = {};
    #pragma unroll
    for (int kk = 0; kk < 16; kk++) {
        int a[4], b[4];
        #pragma unroll
        for (int i = 0; i < 4; i++) a[i] = qs[ty * 4 + i][kk];
        #pragma unroll
        for (int j = 0; j < 4; j++) b[j] = ks[tx * 4 + j][kk];
        #pragma unroll
        for (int i = 0; i < 4; i++)
            #pragma unroll
            for (int j = 0; j < 4; j++)
                acc[i][j] = __dp4a(a[i], b[j], acc[i][j]);
    }

    int8_t* Srow = g_S + (size_t)bh * SEQ * SEQ;
    #pragma unroll
    for (int i = 0; i < 4; i++) {
        int q = q0t + ty * 4 + i;
        #pragma unroll
        for (int j = 0; j < 4; j++) {
            int k = k0t + tx * 4 + j;
            int v = (acc[i][j] * 5) >> 12;       // floor(acc*5/4096), exact
            Srow[(size_t)q * SEQ + k] = (int8_t)clamp_i8(v);
        }
    }
}

// ---------------------------------------------------------------------------
// Kernel 3: ITA softmax scan (sequential over 128 groups of 16 keys per row).
// One thread per row; pure integer, exact replica of the reference lax.scan.
// ---------------------------------------------------------------------------
__global__ void scan_kernel()
{
    int row = blockIdx.x * blockDim.x + threadIdx.x;
    if (row >= NROWS) return;

    const int4* p = (const int4*)(g_S + (size_t)row * SEQ);
    int gmax = -128;
    int ps = 0;

    for (int g = 0; g < SEQ / 16; g++) {
        int4 w = p[g];
        int words[4] = {w.x, w.y, w.z, w.w};
        // group max via SIMD byte max
        int mw = __vmaxs4(__vmaxs4(w.x, w.y), __vmaxs4(w.z, w.w));
        int cmax = -128;
        #pragma unroll
        for (int b = 0; b < 4; b++) {
            int v = (int)(int8_t)((unsigned)mw >> (8 * b));
            cmax = max(cmax, v);
        }
        if (cmax > gmax) {
            int sh = cmax - gmax;
            ps = (sh < 31) ? (ps >> sh) : 0;
            gmax = cmax;
        }
        int es = 0;
        #pragma unroll
        for (int jw = 0; jw < 4; jw++) {
            int wv = words[jw];
            #pragma unroll
            for (int b = 0; b < 4; b++) {
                int xv = (int)(int8_t)((unsigned)wv >> (8 * b));
                int df = gmax - xv;              // >= 0, <= 255
                es += (df < 9) ? (256 >> df) : 0;
            }
        }
        ps += es;
    }
    g_rmax[row] = gmax;
    g_rinv[row] = 65280 / ps;   // exact == floor(65280.0/ps), ps >= 256
}

// ---------------------------------------------------------------------------
// Kernel 4: attn write: attn[k] = inv >> (gmax - x[k]), in-place over g_S.
// One int4 (16 bytes) per thread.
// ---------------------------------------------------------------------------
__global__ void attn_kernel()
{
    size_t i = (size_t)blockIdx.x * blockDim.x + threadIdx.x;
    const size_t n4 = (size_t)BH * SEQ * (SEQ / 16);
    if (i >= n4) return;

    int row = (int)(i / (SEQ / 16));
    int4 w = ((const int4*)g_S)[i];
    int gmax = g_rmax[row];
    int inv  = g_rinv[row];

    int in[4] = {w.x, w.y, w.z, w.w};
    int out[4];
    #pragma unroll
    for (int jw = 0; jw < 4; jw++) {
        unsigned o = 0;
        #pragma unroll
        for (int b = 0; b < 4; b++) {
            int xv = (int)(int8_t)((unsigned)in[jw] >> (8 * b));
            int df = gmax - xv;
            if (df > 31) df = 31;
            unsigned a = (unsigned)(inv >> df);   // <= 255
            o |= a << (8 * b);
        }
        out[jw] = (int)o;
    }
    ((int4*)g_S)[i] = make_int4(out[0], out[1], out[2], out[3]);
}

// ---------------------------------------------------------------------------
// Kernel 5: ctx = requantize(attn @ V, 1, 8) -> int8 [b][n][h*hd]
// grid (32 q-tiles, 24 bh), block 256.  dp4a.u32.s32 over K=2048.
// ---------------------------------------------------------------------------
__global__ void av_kernel()
{
    __shared__ unsigned as_[64][17];
    __shared__ int      vs [64][17];

    const int bh = blockIdx.y;
    const int q0 = blockIdx.x * 64;
    const int tid = threadIdx.x;
    const int tx = tid & 15;
    const int ty = tid >> 4;

    const unsigned* Aw = (const unsigned*)g_S + (size_t)bh * SEQ * (SEQ / 4);
    const int*      Vw = (const int*)g_Vt + (size_t)bh * HD * (SEQ / 4);

    int acc[4][4] = {};

    for (int k0 = 0; k0 < SEQ / 4; k0 += 16) {   // chunk of 64 keys = 16 words
        #pragma unroll
        for (int i = 0; i < 4; i++) {
            int idx = tid + i * 256;
            int r = idx >> 4, c = idx & 15;
            as_[r][c] = Aw[(size_t)(q0 + r) * (SEQ / 4) + k0 + c];
            vs [r][c] = Vw[(size_t)r * (SEQ / 4) + k0 + c];
        }
        __syncthreads();
        #pragma unroll
        for (int kk = 0; kk < 16; kk++) {
            unsigned a[4]; int b[4];
            #pragma unroll
            for (int i = 0; i < 4; i++) a[i] = as_[ty * 4 + i][kk];
            #pragma unroll
            for (int j = 0; j < 4; j++) b[j] = vs[tx * 4 + j][kk];
            #pragma unroll
            for (int i = 0; i < 4; i++)
                #pragma unroll
                for (int j = 0; j < 4; j++)
                    acc[i][j] = dp4a_us(a[i], b[j], acc[i][j]);
        }
        __syncthreads();
    }

    const int b = bh / NHEADS;
    const int h = bh % NHEADS;
    #pragma unroll
    for (int i = 0; i < 4; i++) {
        int q = q0 + ty * 4 + i;
        #pragma unroll
        for (int j = 0; j < 4; j++) {
            int d = tx * 4 + j;
            int v = acc[i][j] >> 8;              // floor(acc/256), exact
            g_ctx[((size_t)b * SEQ + q) * DMODEL + h * HD + d] = (int8_t)clamp_i8(v);
        }
    }
}

// ---------------------------------------------------------------------------
// Kernel 6: out = requantize(ctx @ wo^T + bo, 256, 7) -> float32
// grid (128, 6), block 256
// ---------------------------------------------------------------------------
__global__ void out_kernel(const float* __restrict__ wo, const float* __restrict__ bo,
                           float* __restrict__ out)
{
    __shared__ float cs[64][17];
    __shared__ float ws[64][17];

    const int m0 = blockIdx.x * 64;
    const int n0 = blockIdx.y * 64;
    const int tid = threadIdx.x;
    const int tx = tid & 15;
    const int ty = tid >> 4;

    float acc[4][4] = {};

    for (int k0 = 0; k0 < DMODEL; k0 += 16) {
        #pragma unroll
        for (int i = 0; i < 4; i++) {
            int idx = tid + i * 256;
            int r = idx >> 4, c = idx & 15;
            cs[r][c] = (float)g_ctx[(size_t)(m0 + r) * DMODEL + k0 + c];
            ws[r][c] = wo[(size_t)(n0 + r) * DMODEL + k0 + c];
        }
        __syncthreads();
        #pragma unroll
        for (int kk = 0; kk < 16; kk++) {
            float a[4], b[4];
            #pragma unroll
            for (int i = 0; i < 4; i++) a[i] = cs[ty * 4 + i][kk];
            #pragma unroll
            for (int j = 0; j < 4; j++) b[j] = ws[tx * 4 + j][kk];
            #pragma unroll
            for (int i = 0; i < 4; i++)
                #pragma unroll
                for (int j = 0; j < 4; j++)
                    acc[i][j] += a[i] * b[j];
        }
        __syncthreads();
    }

    #pragma unroll
    for (int i = 0; i < 4; i++) {
        int m = m0 + ty * 4 + i;
        #pragma unroll
        for (int j = 0; j < 4; j++) {
            int c = n0 + tx * 4 + j;
            float v = acc[i][j] + bo[c];
            float r = v * 256.0f;
            r = r * (1.0f / 128.0f);             // exact
            r = floorf(r);
            r = fminf(fmaxf(r, -128.0f), 127.0f);
            out[(size_t)m * DMODEL + c] = r;
        }
    }
}

// ---------------------------------------------------------------------------
extern "C" void kernel_launch(void* const* d_in, const int* in_sizes, int n_in,
                              void* d_out, int out_size)
{
    const float* x  = (const float*)d_in[0];
    const float* wq = (const float*)d_in[1];
    const float* bq = (const float*)d_in[2];
    const float* wk = (const float*)d_in[3];
    const float* bk = (const float*)d_in[4];
    const float* wv = (const float*)d_in[5];
    const float* bv = (const float*)d_in[6];
    const float* wo = (const float*)d_in[7];
    const float* bo = (const float*)d_in[8];
    float* out = (float*)d_out;

    proj_kernel<<<dim3(128, 6, 3), 256>>>(x, wq, bq, wk, bk, wv, bv);
    logits_kernel<<<dim3(32, 32, 24), 256>>>();
    scan_kernel<<<NROWS / 256, 256>>>();
    attn_kernel<<<(unsigned)(((size_t)BH * SEQ * (SEQ / 16)) / 256), 256>>>();
    av_kernel<<<dim3(32, 24), 256>>>();
    out_kernel<<<dim3(128, 6), 256>>>(wo, bo, out);
}

// round 6
// speedup vs baseline: 1.1129x; 1.1129x over previous
#include <cuda_runtime.h>
#include <cstdint>
#include <cstddef>

#define BATCH 4
#define SEQ 2048
#define DMODEL 384
#define NHEADS 6
#define HD 64
#define BH (BATCH*NHEADS)      /* 24 */

// ---------------- scratch (static device arrays; no cudaMalloc allowed) -------
__device__ __align__(16) int8_t g_Q  [(size_t)BH*SEQ*HD];        // [b][h][n][d]
__device__ __align__(16) int8_t g_K  [(size_t)BH*SEQ*HD];        // [b][h][n][d]
__device__ __align__(16) int8_t g_Vt [(size_t)BH*HD*SEQ];        // [b][h][d][n]
__device__ __align__(16) int8_t g_ctx[(size_t)BATCH*SEQ*DMODEL]; // [b][n][h*hd]

__device__ __forceinline__ int dp4a_us(unsigned a, int b, int c) {
    int d;
    asm("dp4a.u32.s32 %0, %1, %2, %3;" : "=r"(d) : "r"(a), "r"(b), "r"(c));
    return d;
}
__device__ __forceinline__ void ffma2(unsigned long long& d,
                                      unsigned long long a, unsigned long long b) {
    asm("fma.rn.f32x2 %0, %1, %2, %0;" : "+l"(d) : "l"(a), "l"(b));
}
__device__ __forceinline__ void unpack2(unsigned long long p, float& lo, float& hi) {
    asm("mov.b64 {%0, %1}, %2;" : "=f"(lo), "=f"(hi) : "l"(p));
}
__device__ __forceinline__ int clamp_i8(int v) {
    return v < -128 ? -128 : (v > 127 ? 127 : v);
}

// ---------------------------------------------------------------------------
// Kernel 1: QKV projection with packed f32x2 FMA.
// Tile 128x128, block 256 (16x16), thread tile 8 rows x 8 cols (4 col-pairs).
// A (x) stored duplicated-transposed in smem so LDS yields (a,a) pairs;
// B (w) stored transposed so LDS.128 yields natural (b0,b1) pairs.
// ---------------------------------------------------------------------------
__global__ void __launch_bounds__(256) proj_kernel(
    const float* __restrict__ x,
    const float* __restrict__ wq, const float* __restrict__ bq,
    const float* __restrict__ wk, const float* __restrict__ bk,
    const float* __restrict__ wv, const float* __restrict__ bv)
{
    __shared__ float xs[16][260];      // [kk][2*row] duplicated pairs
    __shared__ float ws[16][132];      // [kk][n]
    __shared__ int8_t vq[128][132];    // V-output transpose staging (z==2)

    const int z = blockIdx.z;
    const float* w    = (z == 0) ? wq : ((z == 1) ? wk : wv);
    const float* bias = (z == 0) ? bq : ((z == 1) ? bk : bv);
    const int m0 = blockIdx.x * 128;
    const int n0 = blockIdx.y * 128;
    const int tid = threadIdx.x, tx = tid & 15, ty = tid >> 4;

    unsigned long long acc[8][4];
    #pragma unroll
    for (int i = 0; i < 8; i++)
        #pragma unroll
        for (int j = 0; j < 4; j++) acc[i][j] = 0ULL;

    for (int k0 = 0; k0 < DMODEL; k0 += 16) {
        #pragma unroll
        for (int it = 0; it < 8; it++) {
            int r = ty + it * 16;          // 0..127
            float xv = x[(size_t)(m0 + r) * DMODEL + k0 + tx];
            *(float2*)&xs[tx][2 * r] = make_float2(xv, xv);
            ws[tx][r] = w[(size_t)(n0 + r) * DMODEL + k0 + tx];
        }
        __syncthreads();
        #pragma unroll
        for (int kk = 0; kk < 16; kk++) {
            ulonglong2 a01 = *(ulonglong2*)&xs[kk][2 * (ty * 8 + 0)];
            ulonglong2 a23 = *(ulonglong2*)&xs[kk][2 * (ty * 8 + 2)];
            ulonglong2 a45 = *(ulonglong2*)&xs[kk][2 * (ty * 8 + 4)];
            ulonglong2 a67 = *(ulonglong2*)&xs[kk][2 * (ty * 8 + 6)];
            ulonglong2 b01 = *(ulonglong2*)&ws[kk][tx * 8];
            ulonglong2 b23 = *(ulonglong2*)&ws[kk][tx * 8 + 4];
            unsigned long long a[8] = {a01.x, a01.y, a23.x, a23.y,
                                       a45.x, a45.y, a67.x, a67.y};
            unsigned long long b[4] = {b01.x, b01.y, b23.x, b23.y};
            #pragma unroll
            for (int i = 0; i < 8; i++)
                #pragma unroll
                for (int j = 0; j < 4; j++)
                    ffma2(acc[i][j], a[i], b[j]);
        }
        __syncthreads();
    }

    float bb[8];
    #pragma unroll
    for (int e = 0; e < 8; e++) bb[e] = bias[n0 + tx * 8 + e];

    if (z < 2) {
        int8_t* dst = (z == 0) ? g_Q : g_K;
        #pragma unroll
        for (int i = 0; i < 8; i++) {
            int m = m0 + ty * 8 + i;
            int b_ = m >> 11, n = m & 2047;
            int c0 = n0 + tx * 8;
            int h = c0 >> 6, d0 = c0 & 63;
            unsigned wlo = 0, whi = 0;
            #pragma unroll
            for (int jp = 0; jp < 4; jp++) {
                float lo, hi; unpack2(acc[i][jp], lo, hi);
                float r0 = floorf(((lo + bb[2*jp]) * 16384.0f) * (1.0f / 256.0f));
                r0 = fminf(fmaxf(r0, -128.0f), 127.0f);
                float r1 = floorf(((hi + bb[2*jp+1]) * 16384.0f) * (1.0f / 256.0f));
                r1 = fminf(fmaxf(r1, -128.0f), 127.0f);
                unsigned u0 = (unsigned)(unsigned char)(int8_t)(int)r0;
                unsigned u1 = (unsigned)(unsigned char)(int8_t)(int)r1;
                if (jp < 2) { wlo |= u0 << (16*jp);     wlo |= u1 << (16*jp + 8); }
                else        { whi |= u0 << (16*(jp-2)); whi |= u1 << (16*(jp-2) + 8); }
            }
            int* dp = (int*)(dst + ((((size_t)(b_ * NHEADS + h)) * SEQ + n) << 6) + d0);
            dp[0] = (int)wlo; dp[1] = (int)whi;
        }
    } else {
        #pragma unroll
        for (int i = 0; i < 8; i++) {
            int mloc = ty * 8 + i;
            #pragma unroll
            for (int jp = 0; jp < 4; jp++) {
                float lo, hi; unpack2(acc[i][jp], lo, hi);
                float r0 = floorf(((lo + bb[2*jp]) * 16384.0f) * (1.0f / 256.0f));
                r0 = fminf(fmaxf(r0, -128.0f), 127.0f);
                float r1 = floorf(((hi + bb[2*jp+1]) * 16384.0f) * (1.0f / 256.0f));
                r1 = fminf(fmaxf(r1, -128.0f), 127.0f);
                vq[tx * 8 + 2*jp][mloc]     = (int8_t)(int)r0;
                vq[tx * 8 + 2*jp + 1][mloc] = (int8_t)(int)r1;
            }
        }
        __syncthreads();
        int b_ = m0 >> 11;
        int nloc = m0 & 2047;
        #pragma unroll
        for (int it = 0; it < 16; it++) {
            int idx = tid + it * 256;          // 0..4095
            int col = idx >> 5, j4 = idx & 31;
            int word = *(int*)&vq[col][j4 * 4];
            int cg = n0 + col, h = cg >> 6, d = cg & 63;
            ((int*)g_Vt)[((size_t)((b_ * NHEADS + h) * HD + d)) * (SEQ/4) + (nloc >> 2) + j4] = word;
        }
    }
}

// ---------------------------------------------------------------------------
// Kernel 2: fused attention. One block = one (bh, 64-row q-tile).
// Phase 1: logits into 132KB smem strip (dp4a, transposed K tiles, double-buffer)
// Phase 2: exact ITA scan in smem (64 threads)
// Phase 2b: in-place transform logits -> attn bytes
// Phase 3: attn @ V (dp4a.u32.s32) -> g_ctx
// ---------------------------------------------------------------------------
#define SW 516                                    /* padded S row (words) */
#define ATTN_SMEM_INTS (64*SW + 16*68 + 2*16*68 + 128)
#define ATTN_SMEM_BYTES (ATTN_SMEM_INTS * 4)      /* 145664 */

extern __shared__ int smem_raw[];

__global__ void __launch_bounds__(256) attn_fused()
{
    int* SM = smem_raw;
    unsigned* S = (unsigned*)SM;                  // [64][SW]
    int* qs    = SM + 64 * SW;                    // [16][68] transposed Q
    int* ks    = qs + 16 * 68;                    // [2][16][68] K / V tiles
    int* gmaxs = ks + 2 * 16 * 68;                // [64]
    int* invs  = gmaxs + 64;                      // [64]

    const int bh = blockIdx.y;
    const int q0 = blockIdx.x * 64;
    const int tid = threadIdx.x, tx = tid & 15, ty = tid >> 4;

    const int* Qw = (const int*)g_Q + (size_t)bh * SEQ * (HD/4) + (size_t)q0 * (HD/4);
    const int* Kw = (const int*)g_K + (size_t)bh * SEQ * (HD/4);
    const int* Vw = (const int*)g_Vt + (size_t)bh * HD * (SEQ/4);

    // fill Q transposed: qs[c][r]
    #pragma unroll
    for (int it = 0; it < 4; it++) {
        int idx = tid + it * 256;
        qs[(idx & 15) * 68 + (idx >> 4)] = Qw[(idx >> 4) * 16 + (idx & 15)];
    }
    int pre[4];
    #pragma unroll
    for (int it = 0; it < 4; it++) {
        int idx = tid + it * 256;
        pre[it] = Kw[(idx >> 4) * 16 + (idx & 15)];
    }
    #pragma unroll
    for (int it = 0; it < 4; it++) {
        int idx = tid + it * 256;
        ks[(idx & 15) * 68 + (idx >> 4)] = pre[it];
    }
    __syncthreads();

    // -------- Phase 1: logits --------
    for (int t = 0; t < 32; t++) {
        int cur = t & 1;
        if (t + 1 < 32) {
            const int* Kt = Kw + (size_t)(t + 1) * 64 * 16;
            #pragma unroll
            for (int it = 0; it < 4; it++) {
                int idx = tid + it * 256;
                pre[it] = Kt[(idx >> 4) * 16 + (idx & 15)];
            }
        }
        int acc[4][4] = {};
        const int* kb = ks + cur * 16 * 68;
        #pragma unroll
        for (int kk = 0; kk < 16; kk++) {
            int4 av = *(const int4*)&qs[kk * 68 + ty * 4];
            int4 bv = *(const int4*)&kb[kk * 68 + tx * 4];
            int a[4] = {av.x, av.y, av.z, av.w};
            int b[4] = {bv.x, bv.y, bv.z, bv.w};
            #pragma unroll
            for (int i = 0; i < 4; i++)
                #pragma unroll
                for (int j = 0; j < 4; j++)
                    acc[i][j] = __dp4a(a[i], b[j], acc[i][j]);
        }
        #pragma unroll
        for (int i = 0; i < 4; i++) {
            unsigned wrd = 0;
            #pragma unroll
            for (int j = 0; j < 4; j++) {
                int v = clamp_i8((acc[i][j] * 5) >> 12);     // floor(acc*5/4096)
                wrd |= ((unsigned)(unsigned char)(int8_t)v) << (8 * j);
            }
            S[(ty * 4 + i) * SW + t * 16 + tx] = wrd;
        }
        if (t + 1 < 32) {
            int nb = (t + 1) & 1;
            #pragma unroll
            for (int it = 0; it < 4; it++) {
                int idx = tid + it * 256;
                ks[nb * 16 * 68 + (idx & 15) * 68 + (idx >> 4)] = pre[it];
            }
        }
        __syncthreads();
    }

    // -------- Phase 2: exact ITA scan (64 threads, one per row) --------
    if (tid < 64) {
        const int* row = (const int*)&S[tid * SW];
        int gmax = -128, ps = 0;
        for (int g = 0; g < SEQ / 16; g++) {
            int4 wv = *(const int4*)&row[g * 4];
            int words[4] = {wv.x, wv.y, wv.z, wv.w};
            int mw = __vmaxs4(__vmaxs4(wv.x, wv.y), __vmaxs4(wv.z, wv.w));
            int cmax = -128;
            #pragma unroll
            for (int b = 0; b < 4; b++) {
                int v = (int)(int8_t)((unsigned)mw >> (8 * b));
                cmax = max(cmax, v);
            }
            if (cmax > gmax) {
                int sh = cmax - gmax;
                ps = (sh < 31) ? (ps >> sh) : 0;
                gmax = cmax;
            }
            int es = 0;
            #pragma unroll
            for (int jw = 0; jw < 4; jw++) {
                int wvv = words[jw];
                #pragma unroll
                for (int b = 0; b < 4; b++) {
                    int xv = (int)(int8_t)((unsigned)wvv >> (8 * b));
                    int df = gmax - xv;
                    es += (df < 9) ? (256 >> df) : 0;
                }
            }
            ps += es;
        }
        gmaxs[tid] = gmax;
        invs[tid] = 65280 / ps;   // exact == floor(65280.0/ps)
    }
    __syncthreads();

    // -------- Phase 2b: logits -> attn bytes, in place --------
    for (int lin = tid; lin < 64 * 512; lin += 256) {
        int q = lin >> 9, w = lin & 511;
        unsigned xw = S[q * SW + w];
        int gm = gmaxs[q];
        unsigned inv = (unsigned)invs[q];
        unsigned o = 0;
        #pragma unroll
        for (int b = 0; b < 4; b++) {
            int xv = (int)(int8_t)(xw >> (8 * b));
            int df = gm - xv;
            if (df > 31) df = 31;
            o |= (inv >> df) << (8 * b);
        }
        S[q * SW + w] = o;
    }
    __syncthreads();

    // -------- Phase 3: attn @ V --------
    int acc[4][4] = {};
    #pragma unroll
    for (int it = 0; it < 4; it++) {
        int idx = tid + it * 256;
        pre[it] = Vw[(idx >> 4) * (SEQ/4) + (idx & 15)];
    }
    #pragma unroll
    for (int it = 0; it < 4; it++) {
        int idx = tid + it * 256;
        ks[(idx & 15) * 68 + (idx >> 4)] = pre[it];
    }
    __syncthreads();
    for (int t = 0; t < 32; t++) {
        int cur = t & 1;
        if (t + 1 < 32) {
            #pragma unroll
            for (int it = 0; it < 4; it++) {
                int idx = tid + it * 256;
                pre[it] = Vw[(idx >> 4) * (SEQ/4) + (t + 1) * 16 + (idx & 15)];
            }
        }
        const int* vb = ks + cur * 16 * 68;
        #pragma unroll
        for (int kk = 0; kk < 16; kk++) {
            unsigned a[4];
            #pragma unroll
            for (int i = 0; i < 4; i++)
                a[i] = S[(ty * 4 + i) * SW + t * 16 + kk];
            int4 bv = *(const int4*)&vb[kk * 68 + tx * 4];
            int b[4] = {bv.x, bv.y, bv.z, bv.w};
            #pragma unroll
            for (int i = 0; i < 4; i++)
                #pragma unroll
                for (int j = 0; j < 4; j++)
                    acc[i][j] = dp4a_us(a[i], b[j], acc[i][j]);
        }
        if (t + 1 < 32) {
            int nb = (t + 1) & 1;
            #pragma unroll
            for (int it = 0; it < 4; it++) {
                int idx = tid + it * 256;
                ks[nb * 16 * 68 + (idx & 15) * 68 + (idx >> 4)] = pre[it];
            }
        }
        __syncthreads();
    }

    const int b_ = bh / NHEADS, h = bh % NHEADS;
    #pragma unroll
    for (int i = 0; i < 4; i++) {
        unsigned wrd = 0;
        #pragma unroll
        for (int j = 0; j < 4; j++) {
            int v = clamp_i8(acc[i][j] >> 8);     // floor(acc/256)
            wrd |= ((unsigned)(unsigned char)(int8_t)v) << (8 * j);
        }
        ((int*)g_ctx)[((size_t)(b_ * SEQ + q0 + ty * 4 + i)) * (DMODEL/4) + h * 16 + tx] = (int)wrd;
    }
}

// ---------------------------------------------------------------------------
// Kernel 3: out = requantize(ctx @ wo^T + bo, 256, 7) with f32x2 FMA
// ---------------------------------------------------------------------------
__global__ void __launch_bounds__(256) out_kernel(
    const float* __restrict__ wo, const float* __restrict__ bo,
    float* __restrict__ out)
{
    __shared__ float cs[16][260];
    __shared__ float ws[16][132];

    const int m0 = blockIdx.x * 128;
    const int n0 = blockIdx.y * 128;
    const int tid = threadIdx.x, tx = tid & 15, ty = tid >> 4;

    unsigned long long acc[8][4];
    #pragma unroll
    for (int i = 0; i < 8; i++)
        #pragma unroll
        for (int j = 0; j < 4; j++) acc[i][j] = 0ULL;

    for (int k0 = 0; k0 < DMODEL; k0 += 16) {
        #pragma unroll
        for (int it = 0; it < 8; it++) {
            int r = ty + it * 16;
            float cv = (float)g_ctx[(size_t)(m0 + r) * DMODEL + k0 + tx];
            *(float2*)&cs[tx][2 * r] = make_float2(cv, cv);
            ws[tx][r] = wo[(size_t)(n0 + r) * DMODEL + k0 + tx];
        }
        __syncthreads();
        #pragma unroll
        for (int kk = 0; kk < 16; kk++) {
            ulonglong2 a01 = *(ulonglong2*)&cs[kk][2 * (ty * 8 + 0)];
            ulonglong2 a23 = *(ulonglong2*)&cs[kk][2 * (ty * 8 + 2)];
            ulonglong2 a45 = *(ulonglong2*)&cs[kk][2 * (ty * 8 + 4)];
            ulonglong2 a67 = *(ulonglong2*)&cs[kk][2 * (ty * 8 + 6)];
            ulonglong2 b01 = *(ulonglong2*)&ws[kk][tx * 8];
            ulonglong2 b23 = *(ulonglong2*)&ws[kk][tx * 8 + 4];
            unsigned long long a[8] = {a01.x, a01.y, a23.x, a23.y,
                                       a45.x, a45.y, a67.x, a67.y};
            unsigned long long b[4] = {b01.x, b01.y, b23.x, b23.y};
            #pragma unroll
            for (int i = 0; i < 8; i++)
                #pragma unroll
                for (int j = 0; j < 4; j++)
                    ffma2(acc[i][j], a[i], b[j]);
        }
        __syncthreads();
    }

    float bb[8];
    #pragma unroll
    for (int e = 0; e < 8; e++) bb[e] = bo[n0 + tx * 8 + e];

    #pragma unroll
    for (int i = 0; i < 8; i++) {
        int m = m0 + ty * 8 + i;
        #pragma unroll
        for (int jp = 0; jp < 4; jp++) {
            float lo, hi; unpack2(acc[i][jp], lo, hi);
            float r0 = floorf(((lo + bb[2*jp]) * 256.0f) * (1.0f / 128.0f));
            r0 = fminf(fmaxf(r0, -128.0f), 127.0f);
            float r1 = floorf(((hi + bb[2*jp+1]) * 256.0f) * (1.0f / 128.0f));
            r1 = fminf(fmaxf(r1, -128.0f), 127.0f);
            *(float2*)&out[(size_t)m * DMODEL + n0 + tx * 8 + 2*jp] = make_float2(r0, r1);
        }
    }
}

// ---------------------------------------------------------------------------
extern "C" void kernel_launch(void* const* d_in, const int* in_sizes, int n_in,
                              void* d_out, int out_size)
{
    const float* x  = (const float*)d_in[0];
    const float* wq = (const float*)d_in[1];
    const float* bq = (const float*)d_in[2];
    const float* wk = (const float*)d_in[3];
    const float* bk = (const float*)d_in[4];
    const float* wv = (const float*)d_in[5];
    const float* bv = (const float*)d_in[6];
    const float* wo = (const float*)d_in[7];
    const float* bo = (const float*)d_in[8];
    float* out = (float*)d_out;

    cudaFuncSetAttribute(attn_fused, cudaFuncAttributeMaxDynamicSharedMemorySize,
                         ATTN_SMEM_BYTES);

    proj_kernel<<<dim3(64, 3, 3), 256>>>(x, wq, bq, wk, bk, wv, bv);
    attn_fused<<<dim3(32, 24), 256, ATTN_SMEM_BYTES>>>();
    out_kernel<<<dim3(64, 3), 256>>>(wo, bo, out);
}

// round 7
// speedup vs baseline: 1.2134x; 1.0903x over previous
#include <cuda_runtime.h>
#include <cstdint>
#include <cstddef>

#define BATCH 4
#define SEQ 2048
#define DMODEL 384
#define NHEADS 6
#define HD 64
#define BH (BATCH*NHEADS)      /* 24 */

// ---------------- scratch (static device arrays; no cudaMalloc allowed) -------
__device__ __align__(16) int8_t g_Q  [(size_t)BH*SEQ*HD];        // [b][h][n][d]
__device__ __align__(16) int8_t g_K  [(size_t)BH*SEQ*HD];        // [b][h][n][d]
__device__ __align__(16) int8_t g_Vt [(size_t)BH*HD*SEQ];        // [b][h][d][n]
__device__ __align__(16) int8_t g_ctx[(size_t)BATCH*SEQ*DMODEL]; // [b][n][h*hd]

__device__ __forceinline__ int dp4a_us(unsigned a, int b, int c) {
    int d;
    asm("dp4a.u32.s32 %0, %1, %2, %3;" : "=r"(d) : "r"(a), "r"(b), "r"(c));
    return d;
}
__device__ __forceinline__ void ffma2(unsigned long long& d,
                                      unsigned long long a, unsigned long long b) {
    asm("fma.rn.f32x2 %0, %1, %2, %0;" : "+l"(d) : "l"(a), "l"(b));
}
__device__ __forceinline__ unsigned long long pack2(float lo, float hi) {
    unsigned long long p;
    asm("mov.b64 %0, {%1, %2};" : "=l"(p) : "f"(lo), "f"(hi));
    return p;
}
__device__ __forceinline__ void unpack2(unsigned long long p, float& lo, float& hi) {
    asm("mov.b64 {%0, %1}, %2;" : "=f"(lo), "=f"(hi) : "l"(p));
}
__device__ __forceinline__ int clamp_i8(int v) {
    return v < -128 ? -128 : (v > 127 ? 127 : v);
}

// ---------------------------------------------------------------------------
// Kernel 1: QKV projection, packed f32x2 FMA with M-dim pairing.
// Tile 128x128, block 256 (16x16), thread tile 8m x 8n (4 m-pairs).
// A rows transposed in smem -> natural (m,m+1) pairs via LDS.128.
// B loaded natural; (b,b) pairs built with movs (alu pipe).
// launch_bounds(256,2) -> <=128 regs -> 2 blocks/SM (16 warps).
// ---------------------------------------------------------------------------
__global__ void __launch_bounds__(256, 2) proj_kernel(
    const float* __restrict__ x,
    const float* __restrict__ wq, const float* __restrict__ bq,
    const float* __restrict__ wk, const float* __restrict__ bk,
    const float* __restrict__ wv, const float* __restrict__ bv)
{
    __shared__ float xs[16][132];      // [kk][m] natural
    __shared__ float ws[16][132];      // [kk][n] natural
    __shared__ int8_t vq[128][132];    // V-output transpose staging (z==2)

    const int z = blockIdx.z;
    const float* w    = (z == 0) ? wq : ((z == 1) ? wk : wv);
    const float* bias = (z == 0) ? bq : ((z == 1) ? bk : bv);
    const int m0 = blockIdx.x * 128;
    const int n0 = blockIdx.y * 128;
    const int tid = threadIdx.x, tx = tid & 15, ty = tid >> 4;

    unsigned long long acc[4][8];      // [m-pair][n]
    #pragma unroll
    for (int i = 0; i < 4; i++)
        #pragma unroll
        for (int j = 0; j < 8; j++) acc[i][j] = 0ULL;

    for (int k0 = 0; k0 < DMODEL; k0 += 16) {
        #pragma unroll
        for (int it = 0; it < 8; it++) {
            int r = ty + it * 16;          // 0..127
            xs[tx][r] = x[(size_t)(m0 + r) * DMODEL + k0 + tx];
            ws[tx][r] = w[(size_t)(n0 + r) * DMODEL + k0 + tx];
        }
        __syncthreads();
        #pragma unroll
        for (int kk = 0; kk < 16; kk++) {
            ulonglong2 a01 = *(ulonglong2*)&xs[kk][ty * 8];      // pairs m0m1,m2m3
            ulonglong2 a23 = *(ulonglong2*)&xs[kk][ty * 8 + 4];  // pairs m4m5,m6m7
            float4 bA = *(float4*)&ws[kk][tx * 8];
            float4 bB = *(float4*)&ws[kk][tx * 8 + 4];
            unsigned long long a[4] = {a01.x, a01.y, a23.x, a23.y};
            unsigned long long bd[8];
            bd[0] = pack2(bA.x, bA.x); bd[1] = pack2(bA.y, bA.y);
            bd[2] = pack2(bA.z, bA.z); bd[3] = pack2(bA.w, bA.w);
            bd[4] = pack2(bB.x, bB.x); bd[5] = pack2(bB.y, bB.y);
            bd[6] = pack2(bB.z, bB.z); bd[7] = pack2(bB.w, bB.w);
            #pragma unroll
            for (int i = 0; i < 4; i++)
                #pragma unroll
                for (int j = 0; j < 8; j++)
                    ffma2(acc[i][j], a[i], bd[j]);
        }
        __syncthreads();
    }

    float bb[8];
    #pragma unroll
    for (int e = 0; e < 8; e++) bb[e] = bias[n0 + tx * 8 + e];

    if (z < 2) {
        int8_t* dst = (z == 0) ? g_Q : g_K;
        #pragma unroll
        for (int mp = 0; mp < 4; mp++) {
            #pragma unroll
            for (int par = 0; par < 2; par++) {
                int m = m0 + ty * 8 + mp * 2 + par;
                int b_ = m >> 11, n = m & 2047;
                int c0 = n0 + tx * 8;
                int h = c0 >> 6, d0 = c0 & 63;
                unsigned wlo = 0, whi = 0;
                #pragma unroll
                for (int j = 0; j < 8; j++) {
                    float lo, hi; unpack2(acc[mp][j], lo, hi);
                    float v = (par == 0) ? lo : hi;
                    float r = floorf(((v + bb[j]) * 16384.0f) * (1.0f / 256.0f));
                    r = fminf(fmaxf(r, -128.0f), 127.0f);
                    unsigned u = (unsigned)(unsigned char)(int8_t)(int)r;
                    if (j < 4) wlo |= u << (8 * j);
                    else       whi |= u << (8 * (j - 4));
                }
                int* dp = (int*)(dst + ((((size_t)(b_ * NHEADS + h)) * SEQ + n) << 6) + d0);
                dp[0] = (int)wlo; dp[1] = (int)whi;
            }
        }
    } else {
        #pragma unroll
        for (int mp = 0; mp < 4; mp++) {
            #pragma unroll
            for (int j = 0; j < 8; j++) {
                float lo, hi; unpack2(acc[mp][j], lo, hi);
                float r0 = floorf(((lo + bb[j]) * 16384.0f) * (1.0f / 256.0f));
                r0 = fminf(fmaxf(r0, -128.0f), 127.0f);
                float r1 = floorf(((hi + bb[j]) * 16384.0f) * (1.0f / 256.0f));
                r1 = fminf(fmaxf(r1, -128.0f), 127.0f);
                vq[tx * 8 + j][ty * 8 + mp * 2]     = (int8_t)(int)r0;
                vq[tx * 8 + j][ty * 8 + mp * 2 + 1] = (int8_t)(int)r1;
            }
        }
        __syncthreads();
        int b_ = m0 >> 11;
        int nloc = m0 & 2047;
        #pragma unroll
        for (int it = 0; it < 16; it++) {
            int idx = tid + it * 256;          // 0..4095
            int col = idx >> 5, j4 = idx & 31;
            int word = *(int*)&vq[col][j4 * 4];
            int cg = n0 + col, h = cg >> 6, d = cg & 63;
            ((int*)g_Vt)[((size_t)((b_ * NHEADS + h) * HD + d)) * (SEQ/4) + (nloc >> 2) + j4] = word;
        }
    }
}

// ---------------------------------------------------------------------------
// Kernel 2: fused attention, 512 threads/block. One block = (bh, 64-q strip).
// Phase 1: logits -> 132KB smem strip (64x128 tiles, dp4a, double-buffered K)
// Phase 2: exact sequential ITA scan (64 threads)
// Phase 2b: in-place logits -> attn bytes
// Phase 3: attn @ V with warp-uniform attn loads (broadcast) -> g_ctx
// ---------------------------------------------------------------------------
#define SW 516                                    /* padded S row (words) */
#define ATTN_SMEM_INTS (64*SW + 16*68 + 2*16*132 + 128)
#define ATTN_SMEM_BYTES (ATTN_SMEM_INTS * 4)

extern __shared__ int smem_raw[];

__global__ void __launch_bounds__(512) attn_fused()
{
    int* SM = smem_raw;
    unsigned* S = (unsigned*)SM;                  // [64][SW]
    int* qs    = SM + 64 * SW;                    // [16][68]  transposed Q
    int* kb    = qs + 16 * 68;                    // [2][16][132] K/V tiles (transposed)
    int* gmaxs = kb + 2 * 16 * 132;               // [64]
    int* invs  = gmaxs + 64;                      // [64]

    const int bh = blockIdx.y;
    const int q0 = blockIdx.x * 64;
    const int tid = threadIdx.x;
    const int tx = tid & 31, ty = tid >> 5;       // ty 0..15 (warp id)

    const int* Qw = (const int*)g_Q + (size_t)bh * SEQ * (HD/4) + (size_t)q0 * (HD/4);
    const int* Kw = (const int*)g_K + (size_t)bh * SEQ * (HD/4);
    const int* Vw = (const int*)g_Vt + (size_t)bh * HD * (SEQ/4);

    // Q transposed: qs[w][q]
    #pragma unroll
    for (int it = 0; it < 2; it++) {
        int idx = tid + it * 512;                  // 0..1023
        qs[(idx & 15) * 68 + (idx >> 4)] = Qw[(idx >> 4) * 16 + (idx & 15)];
    }
    // prefetch K tile 0 (128 rows x 16 words)
    int pre[4];
    #pragma unroll
    for (int it = 0; it < 4; it++) {
        int idx = tid + it * 512;                  // 0..2047
        pre[it] = Kw[(idx >> 4) * 16 + (idx & 15)];
    }
    #pragma unroll
    for (int it = 0; it < 4; it++) {
        int idx = tid + it * 512;
        kb[(idx & 15) * 132 + (idx >> 4)] = pre[it];
    }
    __syncthreads();

    // -------- Phase 1: logits (16 tiles of 128 keys) --------
    for (int t = 0; t < 16; t++) {
        int cur = t & 1;
        if (t + 1 < 16) {
            const int* Kt = Kw + (size_t)(t + 1) * 128 * 16;
            #pragma unroll
            for (int it = 0; it < 4; it++) {
                int idx = tid + it * 512;
                pre[it] = Kt[(idx >> 4) * 16 + (idx & 15)];
            }
        }
        int acc[4][4] = {};
        const int* kbc = kb + cur * 16 * 132;
        #pragma unroll
        for (int kk = 0; kk < 16; kk++) {
            int4 av = *(const int4*)&qs[kk * 68 + ty * 4];      // 4 q rows
            int4 bv = *(const int4*)&kbc[kk * 132 + tx * 4];    // 4 keys
            int a[4] = {av.x, av.y, av.z, av.w};
            int b[4] = {bv.x, bv.y, bv.z, bv.w};
            #pragma unroll
            for (int i = 0; i < 4; i++)
                #pragma unroll
                for (int j = 0; j < 4; j++)
                    acc[i][j] = __dp4a(a[i], b[j], acc[i][j]);
        }
        #pragma unroll
        for (int i = 0; i < 4; i++) {
            unsigned wrd = 0;
            #pragma unroll
            for (int j = 0; j < 4; j++) {
                int v = clamp_i8((acc[i][j] * 5) >> 12);         // floor(acc*5/4096)
                wrd |= ((unsigned)(unsigned char)(int8_t)v) << (8 * j);
            }
            S[(ty * 4 + i) * SW + t * 32 + tx] = wrd;
        }
        if (t + 1 < 16) {
            int nb = (t + 1) & 1;
            #pragma unroll
            for (int it = 0; it < 4; it++) {
                int idx = tid + it * 512;
                kb[nb * 16 * 132 + (idx & 15) * 132 + (idx >> 4)] = pre[it];
            }
        }
        __syncthreads();
    }

    // -------- Phase 2: exact ITA scan, one thread per q row --------
    if (tid < 64) {
        const int* row = (const int*)&S[tid * SW];
        int gmax = -128, ps = 0;
        for (int g = 0; g < SEQ / 16; g++) {
            int4 wv = *(const int4*)&row[g * 4];
            int words[4] = {wv.x, wv.y, wv.z, wv.w};
            int mw = __vmaxs4(__vmaxs4(wv.x, wv.y), __vmaxs4(wv.z, wv.w));
            int cmax = -128;
            #pragma unroll
            for (int b = 0; b < 4; b++) {
                int v = (int)(int8_t)((unsigned)mw >> (8 * b));
                cmax = max(cmax, v);
            }
            if (cmax > gmax) {
                int sh = cmax - gmax;
                ps = (sh < 31) ? (ps >> sh) : 0;
                gmax = cmax;
            }
            int es = 0;
            #pragma unroll
            for (int jw = 0; jw < 4; jw++) {
                int wvv = words[jw];
                #pragma unroll
                for (int b = 0; b < 4; b++) {
                    int xv = (int)(int8_t)((unsigned)wvv >> (8 * b));
                    int df = gmax - xv;
                    es += (df < 9) ? (256 >> df) : 0;
                }
            }
            ps += es;
        }
        gmaxs[tid] = gmax;
        invs[tid] = 65280 / ps;   // exact == floor(65280.0/ps)
    }
    __syncthreads();

    // -------- Phase 2b: logits -> attn bytes, in place --------
    for (int lin = tid; lin < 64 * 512; lin += 512) {
        int q = lin >> 9, w = lin & 511;
        unsigned xw = S[q * SW + w];
        int gm = gmaxs[q];
        unsigned inv = (unsigned)invs[q];
        unsigned o = 0;
        #pragma unroll
        for (int b = 0; b < 4; b++) {
            int xv = (int)(int8_t)(xw >> (8 * b));
            int df = gm - xv;
            if (df > 31) df = 31;
            o |= (inv >> df) << (8 * b);
        }
        S[q * SW + w] = o;
    }

    // -------- Phase 3: attn @ V (32 tiles of 64 keys) --------
    // warp covers d (tx -> 2 cols), ty covers 4 q rows -> attn loads broadcast
    int acc2[4][2] = {};
    #pragma unroll
    for (int it = 0; it < 2; it++) {
        int idx = tid + it * 512;                  // 0..1023: d=idx>>4, w=idx&15
        pre[it] = Vw[(idx >> 4) * (SEQ/4) + (idx & 15)];
    }
    __syncthreads();                               // also covers phase 2b completion
    #pragma unroll
    for (int it = 0; it < 2; it++) {
        int idx = tid + it * 512;
        kb[(idx & 15) * 132 + (idx >> 4)] = pre[it];
    }
    __syncthreads();

    for (int t = 0; t < 32; t++) {
        int cur = t & 1;
        if (t + 1 < 32) {
            #pragma unroll
            for (int it = 0; it < 2; it++) {
                int idx = tid + it * 512;
                pre[it] = Vw[(idx >> 4) * (SEQ/4) + (t + 1) * 16 + (idx & 15)];
            }
        }
        const int* vbc = kb + cur * 16 * 132;
        #pragma unroll
        for (int kk = 0; kk < 16; kk++) {
            int2 bv = *(const int2*)&vbc[kk * 132 + tx * 2];
            #pragma unroll
            for (int i = 0; i < 4; i++) {
                unsigned a = S[(ty * 4 + i) * SW + t * 16 + kk];   // broadcast
                acc2[i][0] = dp4a_us(a, bv.x, acc2[i][0]);
                acc2[i][1] = dp4a_us(a, bv.y, acc2[i][1]);
            }
        }
        if (t + 1 < 32) {
            int nb = (t + 1) & 1;
            #pragma unroll
            for (int it = 0; it < 2; it++) {
                int idx = tid + it * 512;
                kb[nb * 16 * 132 + (idx & 15) * 132 + (idx >> 4)] = pre[it];
            }
        }
        __syncthreads();
    }

    const int b_ = bh / NHEADS, h = bh % NHEADS;
    #pragma unroll
    for (int i = 0; i < 4; i++) {
        int q = q0 + ty * 4 + i;
        int8_t* dst = g_ctx + ((size_t)(b_ * SEQ + q)) * DMODEL + h * HD + tx * 2;
        dst[0] = (int8_t)clamp_i8(acc2[i][0] >> 8);   // floor(acc/256)
        dst[1] = (int8_t)clamp_i8(acc2[i][1] >> 8);
    }
}

// ---------------------------------------------------------------------------
// Kernel 3: out = requantize(ctx @ wo^T + bo, 256, 7), f32x2 M-pair scheme
// ---------------------------------------------------------------------------
__global__ void __launch_bounds__(256, 2) out_kernel(
    const float* __restrict__ wo, const float* __restrict__ bo,
    float* __restrict__ out)
{
    __shared__ float cs[16][132];
    __shared__ float ws[16][132];

    const int m0 = blockIdx.x * 128;
    const int n0 = blockIdx.y * 128;
    const int tid = threadIdx.x, tx = tid & 15, ty = tid >> 4;

    unsigned long long acc[4][8];
    #pragma unroll
    for (int i = 0; i < 4; i++)
        #pragma unroll
        for (int j = 0; j < 8; j++) acc[i][j] = 0ULL;

    for (int k0 = 0; k0 < DMODEL; k0 += 16) {
        #pragma unroll
        for (int it = 0; it < 8; it++) {
            int r = ty + it * 16;
            cs[tx][r] = (float)g_ctx[(size_t)(m0 + r) * DMODEL + k0 + tx];
            ws[tx][r] = wo[(size_t)(n0 + r) * DMODEL + k0 + tx];
        }
        __syncthreads();
        #pragma unroll
        for (int kk = 0; kk < 16; kk++) {
            ulonglong2 a01 = *(ulonglong2*)&cs[kk][ty * 8];
            ulonglong2 a23 = *(ulonglong2*)&cs[kk][ty * 8 + 4];
            float4 bA = *(float4*)&ws[kk][tx * 8];
            float4 bB = *(float4*)&ws[kk][tx * 8 + 4];
            unsigned long long a[4] = {a01.x, a01.y, a23.x, a23.y};
            unsigned long long bd[8];
            bd[0] = pack2(bA.x, bA.x); bd[1] = pack2(bA.y, bA.y);
            bd[2] = pack2(bA.z, bA.z); bd[3] = pack2(bA.w, bA.w);
            bd[4] = pack2(bB.x, bB.x); bd[5] = pack2(bB.y, bB.y);
            bd[6] = pack2(bB.z, bB.z); bd[7] = pack2(bB.w, bB.w);
            #pragma unroll
            for (int i = 0; i < 4; i++)
                #pragma unroll
                for (int j = 0; j < 8; j++)
                    ffma2(acc[i][j], a[i], bd[j]);
        }
        __syncthreads();
    }

    float bb[8];
    #pragma unroll
    for (int e = 0; e < 8; e++) bb[e] = bo[n0 + tx * 8 + e];

    #pragma unroll
    for (int mp = 0; mp < 4; mp++) {
        #pragma unroll
        for (int par = 0; par < 2; par++) {
            int m = m0 + ty * 8 + mp * 2 + par;
            float vals[8];
            #pragma unroll
            for (int j = 0; j < 8; j++) {
                float lo, hi; unpack2(acc[mp][j], lo, hi);
                float v = (par == 0) ? lo : hi;
                float r = floorf(((v + bb[j]) * 256.0f) * (1.0f / 128.0f));
                vals[j] = fminf(fmaxf(r, -128.0f), 127.0f);
            }
            float4* op = (float4*)&out[(size_t)m * DMODEL + n0 + tx * 8];
            op[0] = make_float4(vals[0], vals[1], vals[2], vals[3]);
            op[1] = make_float4(vals[4], vals[5], vals[6], vals[7]);
        }
    }
}

// ---------------------------------------------------------------------------
extern "C" void kernel_launch(void* const* d_in, const int* in_sizes, int n_in,
                              void* d_out, int out_size)
{
    const float* x  = (const float*)d_in[0];
    const float* wq = (const float*)d_in[1];
    const float* bq = (const float*)d_in[2];
    const float* wk = (const float*)d_in[3];
    const float* bk = (const float*)d_in[4];
    const float* wv = (const float*)d_in[5];
    const float* bv = (const float*)d_in[6];
    const float* wo = (const float*)d_in[7];
    const float* bo = (const float*)d_in[8];
    float* out = (float*)d_out;

    cudaFuncSetAttribute(attn_fused, cudaFuncAttributeMaxDynamicSharedMemorySize,
                         ATTN_SMEM_BYTES);

    proj_kernel<<<dim3(64, 3, 3), 256>>>(x, wq, bq, wk, bk, wv, bv);
    attn_fused<<<dim3(32, 24), 512, ATTN_SMEM_BYTES>>>();
    out_kernel<<<dim3(64, 3), 256>>>(wo, bo, out);
}

// round 8
// speedup vs baseline: 1.2138x; 1.0003x over previous
#include <cuda_runtime.h>
#include <cstdint>
#include <cstddef>

#define BATCH 4
#define SEQ 2048
#define DMODEL 384
#define NHEADS 6
#define HD 64
#define BH (BATCH*NHEADS)      /* 24 */

// ---------------- scratch (static device arrays; no cudaMalloc allowed) -------
__device__ __align__(16) int8_t g_Q  [(size_t)BH*SEQ*HD];        // [b][h][n][d]
__device__ __align__(16) int8_t g_K  [(size_t)BH*SEQ*HD];        // [b][h][n][d]
// V packed words: word (bh, nblk, d) = V[nblk*4 .. +3][d] bytes (packed along n)
__device__ __align__(16) int8_t g_Vp [(size_t)BH*(SEQ/4)*HD*4];  // [bh][nblk 512][d 64] int32 words
__device__ __align__(16) int8_t g_ctx[(size_t)BATCH*SEQ*DMODEL]; // [b][n][h*hd]

__device__ __forceinline__ int dp4a_us(unsigned a, int b, int c) {
    int d;
    asm("dp4a.u32.s32 %0, %1, %2, %3;" : "=r"(d) : "r"(a), "r"(b), "r"(c));
    return d;
}
__device__ __forceinline__ void ffma2(unsigned long long& d,
                                      unsigned long long a, unsigned long long b) {
    asm("fma.rn.f32x2 %0, %1, %2, %0;" : "+l"(d) : "l"(a), "l"(b));
}
__device__ __forceinline__ unsigned long long pack2(float lo, float hi) {
    unsigned long long p;
    asm("mov.b64 %0, {%1, %2};" : "=l"(p) : "f"(lo), "f"(hi));
    return p;
}
__device__ __forceinline__ void unpack2(unsigned long long p, float& lo, float& hi) {
    asm("mov.b64 {%0, %1}, %2;" : "=f"(lo), "=f"(hi) : "l"(p));
}
__device__ __forceinline__ int clamp_i8(int v) {
    return v < -128 ? -128 : (v > 127 ? 127 : v);
}
__device__ __forceinline__ unsigned pack_bytes(int v0, int v1, int v2, int v3) {
    return  ((unsigned)(unsigned char)(int8_t)v0)
          | (((unsigned)(unsigned char)(int8_t)v1) << 8)
          | (((unsigned)(unsigned char)(int8_t)v2) << 16)
          | (((unsigned)(unsigned char)(int8_t)v3) << 24);
}

// ---------------------------------------------------------------------------
// Kernel 1: QKV projection (f32x2 FMA, M-dim pairing). Unchanged math from R6;
// z==2 now emits g_Vp in [bh][nblk][d] word layout for the AV phase.
// ---------------------------------------------------------------------------
__global__ void __launch_bounds__(256, 2) proj_kernel(
    const float* __restrict__ x,
    const float* __restrict__ wq, const float* __restrict__ bq,
    const float* __restrict__ wk, const float* __restrict__ bk,
    const float* __restrict__ wv, const float* __restrict__ bv)
{
    __shared__ float xs[16][132];      // [kk][m]
    __shared__ float ws[16][132];      // [kk][n]
    __shared__ int8_t vq[128][132];    // V transpose staging (z==2)

    const int z = blockIdx.z;
    const float* w    = (z == 0) ? wq : ((z == 1) ? wk : wv);
    const float* bias = (z == 0) ? bq : ((z == 1) ? bk : bv);
    const int m0 = blockIdx.x * 128;
    const int n0 = blockIdx.y * 128;
    const int tid = threadIdx.x, tx = tid & 15, ty = tid >> 4;

    unsigned long long acc[4][8];
    #pragma unroll
    for (int i = 0; i < 4; i++)
        #pragma unroll
        for (int j = 0; j < 8; j++) acc[i][j] = 0ULL;

    for (int k0 = 0; k0 < DMODEL; k0 += 16) {
        #pragma unroll
        for (int it = 0; it < 8; it++) {
            int r = ty + it * 16;
            xs[tx][r] = x[(size_t)(m0 + r) * DMODEL + k0 + tx];
            ws[tx][r] = w[(size_t)(n0 + r) * DMODEL + k0 + tx];
        }
        __syncthreads();
        #pragma unroll
        for (int kk = 0; kk < 16; kk++) {
            ulonglong2 a01 = *(ulonglong2*)&xs[kk][ty * 8];
            ulonglong2 a23 = *(ulonglong2*)&xs[kk][ty * 8 + 4];
            float4 bA = *(float4*)&ws[kk][tx * 8];
            float4 bB = *(float4*)&ws[kk][tx * 8 + 4];
            unsigned long long a[4] = {a01.x, a01.y, a23.x, a23.y};
            unsigned long long bd[8];
            bd[0] = pack2(bA.x, bA.x); bd[1] = pack2(bA.y, bA.y);
            bd[2] = pack2(bA.z, bA.z); bd[3] = pack2(bA.w, bA.w);
            bd[4] = pack2(bB.x, bB.x); bd[5] = pack2(bB.y, bB.y);
            bd[6] = pack2(bB.z, bB.z); bd[7] = pack2(bB.w, bB.w);
            #pragma unroll
            for (int i = 0; i < 4; i++)
                #pragma unroll
                for (int j = 0; j < 8; j++)
                    ffma2(acc[i][j], a[i], bd[j]);
        }
        __syncthreads();
    }

    float bb[8];
    #pragma unroll
    for (int e = 0; e < 8; e++) bb[e] = bias[n0 + tx * 8 + e];

    if (z < 2) {
        int8_t* dst = (z == 0) ? g_Q : g_K;
        #pragma unroll
        for (int mp = 0; mp < 4; mp++) {
            #pragma unroll
            for (int par = 0; par < 2; par++) {
                int m = m0 + ty * 8 + mp * 2 + par;
                int b_ = m >> 11, n = m & 2047;
                int c0 = n0 + tx * 8;
                int h = c0 >> 6, d0 = c0 & 63;
                unsigned wlo = 0, whi = 0;
                #pragma unroll
                for (int j = 0; j < 8; j++) {
                    float lo, hi; unpack2(acc[mp][j], lo, hi);
                    float v = (par == 0) ? lo : hi;
                    float r = floorf(((v + bb[j]) * 16384.0f) * (1.0f / 256.0f));
                    r = fminf(fmaxf(r, -128.0f), 127.0f);
                    unsigned u = (unsigned)(unsigned char)(int8_t)(int)r;
                    if (j < 4) wlo |= u << (8 * j);
                    else       whi |= u << (8 * (j - 4));
                }
                int* dp = (int*)(dst + ((((size_t)(b_ * NHEADS + h)) * SEQ + n) << 6) + d0);
                dp[0] = (int)wlo; dp[1] = (int)whi;
            }
        }
    } else {
        #pragma unroll
        for (int mp = 0; mp < 4; mp++) {
            #pragma unroll
            for (int j = 0; j < 8; j++) {
                float lo, hi; unpack2(acc[mp][j], lo, hi);
                float r0 = floorf(((lo + bb[j]) * 16384.0f) * (1.0f / 256.0f));
                r0 = fminf(fmaxf(r0, -128.0f), 127.0f);
                float r1 = floorf(((hi + bb[j]) * 16384.0f) * (1.0f / 256.0f));
                r1 = fminf(fmaxf(r1, -128.0f), 127.0f);
                vq[tx * 8 + j][ty * 8 + mp * 2]     = (int8_t)(int)r0;
                vq[tx * 8 + j][ty * 8 + mp * 2 + 1] = (int8_t)(int)r1;
            }
        }
        __syncthreads();
        int b_ = m0 >> 11;
        int nloc = m0 & 2047;
        #pragma unroll
        for (int it = 0; it < 16; it++) {
            int idx = tid + it * 256;              // 0..4095
            int col = idx & 127;                   // feature col (fast -> coalesced d)
            int j4  = idx >> 7;                    // nblk within tile (0..31)
            int word = *(int*)&vq[col][j4 * 4];
            int cg = n0 + col, h = cg >> 6, d = cg & 63;
            size_t nblk = (size_t)((nloc >> 2) + j4);
            ((int*)g_Vp)[((size_t)(b_ * NHEADS + h) * (SEQ/4) + nblk) * HD + d] = word;
        }
    }
}

// ---------------------------------------------------------------------------
// Kernel 2: fused attention, 512 threads. One block = (bh, 64-q strip).
// Phase 1: logits, 64q x 256key tiles, thread 4q x 8keys (dp4a-dense)
// Phase 2: exact sequential ITA scan (64 threads)
// Phase 2b: logits -> attn bytes in place
// Phase 3: attn @ V, k-split x4, thread 4q x 8d, smem reduction
// ---------------------------------------------------------------------------
#define SW 516                                    /* padded S row (words) */
#define KP 260                                    /* K tile row pad (words) */
#define VPAD 68                                   /* V tile row pad (words) */
#define U_INTS 16384                              /* union: kb / vb / red */
#define ATTN_SMEM_INTS (64*SW + 16*68 + U_INTS + 128)
#define ATTN_SMEM_BYTES (ATTN_SMEM_INTS * 4)

extern __shared__ int smem_raw[];

__global__ void __launch_bounds__(512) attn_fused()
{
    int* SM = smem_raw;
    unsigned* S = (unsigned*)SM;                  // [64][SW]
    int* qs    = SM + 64 * SW;                    // [16][68] transposed Q
    int* U     = qs + 16 * 68;                    // union region (16384 ints)
    int* gmaxs = U + U_INTS;                      // [64]
    int* invs  = gmaxs + 64;                      // [64]

    const int bh = blockIdx.y;
    const int q0 = blockIdx.x * 64;
    const int tid = threadIdx.x;
    const int lane = tid & 31, warp = tid >> 5;   // 16 warps

    const int* Qw = (const int*)g_Q + (size_t)bh * SEQ * (HD/4) + (size_t)q0 * (HD/4);
    const int* Kw = (const int*)g_K + (size_t)bh * SEQ * (HD/4);
    const int* Vw = (const int*)g_Vp + (size_t)bh * (SEQ/4) * HD;

    // ---- Q transposed: qs[kk][qrow] (1024 words) ----
    #pragma unroll
    for (int it = 0; it < 2; it++) {
        int idx = tid + it * 512;
        qs[(idx & 15) * 68 + (idx >> 4)] = Qw[idx];
    }
    // ---- prefetch K tile 0 (256 rows x 16 words = 4096) ----
    int pre[8];
    #pragma unroll
    for (int it = 0; it < 8; it++) pre[it] = Kw[tid + it * 512];
    #pragma unroll
    for (int it = 0; it < 8; it++) {
        int idx = tid + it * 512;
        U[(idx & 15) * KP + (idx >> 4)] = pre[it];
    }
    __syncthreads();

    // -------- Phase 1: logits, 8 tiles of 256 keys --------
    for (int t = 0; t < 8; t++) {
        int cur = t & 1;
        if (t + 1 < 8) {
            const int* Kt = Kw + (size_t)(t + 1) * 4096;
            #pragma unroll
            for (int it = 0; it < 8; it++) pre[it] = Kt[tid + it * 512];
        }
        const int* kbc = U + cur * 16 * KP;
        int acc[4][8];
        #pragma unroll
        for (int i = 0; i < 4; i++)
            #pragma unroll
            for (int j = 0; j < 8; j++) acc[i][j] = 0;
        #pragma unroll
        for (int kk = 0; kk < 16; kk++) {
            int a[4];
            #pragma unroll
            for (int i = 0; i < 4; i++) a[i] = qs[kk * 68 + warp * 4 + i];  // broadcast
            int4 b0 = *(const int4*)&kbc[kk * KP + lane * 8];
            int4 b1 = *(const int4*)&kbc[kk * KP + lane * 8 + 4];
            int b[8] = {b0.x, b0.y, b0.z, b0.w, b1.x, b1.y, b1.z, b1.w};
            #pragma unroll
            for (int i = 0; i < 4; i++)
                #pragma unroll
                for (int j = 0; j < 8; j++)
                    acc[i][j] = __dp4a(a[i], b[j], acc[i][j]);
        }
        #pragma unroll
        for (int i = 0; i < 4; i++) {
            unsigned w0 = pack_bytes(clamp_i8((acc[i][0]*5) >> 12), clamp_i8((acc[i][1]*5) >> 12),
                                     clamp_i8((acc[i][2]*5) >> 12), clamp_i8((acc[i][3]*5) >> 12));
            unsigned w1 = pack_bytes(clamp_i8((acc[i][4]*5) >> 12), clamp_i8((acc[i][5]*5) >> 12),
                                     clamp_i8((acc[i][6]*5) >> 12), clamp_i8((acc[i][7]*5) >> 12));
            *(int2*)&S[(warp * 4 + i) * SW + t * 64 + lane * 2] = make_int2((int)w0, (int)w1);
        }
        __syncthreads();
        if (t + 1 < 8) {
            int nb = (t + 1) & 1;
            #pragma unroll
            for (int it = 0; it < 8; it++) {
                int idx = tid + it * 512;
                U[nb * 16 * KP + (idx & 15) * KP + (idx >> 4)] = pre[it];
            }
            __syncthreads();
        }
    }

    // -------- Phase 2: exact ITA scan, one thread per q row --------
    if (tid < 64) {
        const int* row = (const int*)&S[tid * SW];
        int gmax = -128, ps = 0;
        for (int g = 0; g < SEQ / 16; g++) {
            int4 wv = *(const int4*)&row[g * 4];
            int words[4] = {wv.x, wv.y, wv.z, wv.w};
            int mw = __vmaxs4(__vmaxs4(wv.x, wv.y), __vmaxs4(wv.z, wv.w));
            int cmax = -128;
            #pragma unroll
            for (int b = 0; b < 4; b++) {
                int v = (int)(int8_t)((unsigned)mw >> (8 * b));
                cmax = max(cmax, v);
            }
            if (cmax > gmax) {
                int sh = cmax - gmax;
                ps = (sh < 31) ? (ps >> sh) : 0;
                gmax = cmax;
            }
            int es = 0;
            #pragma unroll
            for (int jw = 0; jw < 4; jw++) {
                int wvv = words[jw];
                #pragma unroll
                for (int b = 0; b < 4; b++) {
                    int xv = (int)(int8_t)((unsigned)wvv >> (8 * b));
                    int df = gmax - xv;
                    es += (df < 9) ? (256 >> df) : 0;
                }
            }
            ps += es;
        }
        gmaxs[tid] = gmax;
        invs[tid] = 65280 / ps;   // exact == floor(65280.0/ps)
    }
    __syncthreads();

    // ---- prefetch V tile 0 while doing phase 2b ----
    #pragma unroll
    for (int it = 0; it < 8; it++) pre[it] = Vw[tid + it * 512];

    // -------- Phase 2b: logits -> attn bytes, in place --------
    {
        int q = tid >> 3;                 // 64 rows, 8 threads per row
        int wbase = (tid & 7) * 64;       // 64 words each
        int gm = gmaxs[q];
        unsigned inv = (unsigned)invs[q];
        for (int w = wbase; w < wbase + 64; w++) {
            unsigned xw = S[q * SW + w];
            unsigned o = 0;
            #pragma unroll
            for (int b = 0; b < 4; b++) {
                int xv = (int)(int8_t)(xw >> (8 * b));
                int df = gm - xv;
                if (df > 31) df = 31;
                o |= (inv >> df) << (8 * b);
            }
            S[q * SW + w] = o;
        }
    }
    __syncthreads();
    #pragma unroll
    for (int it = 0; it < 8; it++) {
        int idx = tid + it * 512;
        U[(idx >> 6) * VPAD + (idx & 63)] = pre[it];   // vb[kwl][d]
    }
    __syncthreads();

    // -------- Phase 3: attn @ V, 8 tiles of 64 kwords, k-split x4 --------
    const int wq = warp & 3;              // q quarter
    const int wk = warp >> 2;             // k quarter
    const int lq = lane >> 3;             // q sub (4)
    const int ld = lane & 7;              // d group (8)
    const int qr0 = wq * 16 + lq * 4;     // thread's first q row

    int acc3[4][8];
    #pragma unroll
    for (int i = 0; i < 4; i++)
        #pragma unroll
        for (int j = 0; j < 8; j++) acc3[i][j] = 0;

    for (int t = 0; t < 8; t++) {
        int cur = t & 1;
        if (t + 1 < 8) {
            const int* Vt = Vw + (size_t)(t + 1) * 4096;
            #pragma unroll
            for (int it = 0; it < 8; it++) pre[it] = Vt[tid + it * 512];
        }
        const int* vbc = U + cur * 64 * VPAD;
        #pragma unroll
        for (int kki = 0; kki < 16; kki++) {
            int kwl = wk * 16 + kki;
            unsigned a[4];
            #pragma unroll
            for (int i = 0; i < 4; i++)
                a[i] = S[(qr0 + i) * SW + t * 64 + kwl];          // 4-distinct broadcast
            int4 b0 = *(const int4*)&vbc[kwl * VPAD + ld * 8];
            int4 b1 = *(const int4*)&vbc[kwl * VPAD + ld * 8 + 4];
            int b[8] = {b0.x, b0.y, b0.z, b0.w, b1.x, b1.y, b1.z, b1.w};
            #pragma unroll
            for (int i = 0; i < 4; i++)
                #pragma unroll
                for (int j = 0; j < 8; j++)
                    acc3[i][j] = dp4a_us(a[i], b[j], acc3[i][j]);
        }
        __syncthreads();
        if (t + 1 < 8) {
            int nb = (t + 1) & 1;
            #pragma unroll
            for (int it = 0; it < 8; it++) {
                int idx = tid + it * 512;
                U[nb * 64 * VPAD + (idx >> 6) * VPAD + (idx & 63)] = pre[it];
            }
            __syncthreads();
        }
    }

    // ---- reduction across the 4 k-groups via union region ----
    __syncthreads();                       // all vb reads done; reuse U as red[4][64][64]
    #pragma unroll
    for (int i = 0; i < 4; i++) {
        *(int4*)&U[wk * 4096 + (qr0 + i) * 64 + ld * 8]     = make_int4(acc3[i][0], acc3[i][1], acc3[i][2], acc3[i][3]);
        *(int4*)&U[wk * 4096 + (qr0 + i) * 64 + ld * 8 + 4] = make_int4(acc3[i][4], acc3[i][5], acc3[i][6], acc3[i][7]);
    }
    __syncthreads();

    {
        const int b_ = bh / NHEADS, h = bh % NHEADS;
        int q = tid >> 3;
        int d0 = (tid & 7) * 8;
        int4 s0 = make_int4(0,0,0,0), s1 = make_int4(0,0,0,0);
        #pragma unroll
        for (int g = 0; g < 4; g++) {
            int4 a0 = *(const int4*)&U[g * 4096 + q * 64 + d0];
            int4 a1 = *(const int4*)&U[g * 4096 + q * 64 + d0 + 4];
            s0.x += a0.x; s0.y += a0.y; s0.z += a0.z; s0.w += a0.w;
            s1.x += a1.x; s1.y += a1.y; s1.z += a1.z; s1.w += a1.w;
        }
        unsigned lo = pack_bytes(clamp_i8(s0.x >> 8), clamp_i8(s0.y >> 8),
                                 clamp_i8(s0.z >> 8), clamp_i8(s0.w >> 8));
        unsigned hi = pack_bytes(clamp_i8(s1.x >> 8), clamp_i8(s1.y >> 8),
                                 clamp_i8(s1.z >> 8), clamp_i8(s1.w >> 8));
        *(int2*)(g_ctx + ((size_t)(b_ * SEQ + q0 + q)) * DMODEL + h * HD + d0) = make_int2((int)lo, (int)hi);
    }
}

// ---------------------------------------------------------------------------
// Kernel 3: out = requantize(ctx @ wo^T + bo, 256, 7), f32x2 M-pair scheme
// ---------------------------------------------------------------------------
__global__ void __launch_bounds__(256, 2) out_kernel(
    const float* __restrict__ wo, const float* __restrict__ bo,
    float* __restrict__ out)
{
    __shared__ float cs[16][132];
    __shared__ float ws[16][132];

    const int m0 = blockIdx.x * 128;
    const int n0 = blockIdx.y * 128;
    const int tid = threadIdx.x, tx = tid & 15, ty = tid >> 4;

    unsigned long long acc[4][8];
    #pragma unroll
    for (int i = 0; i < 4; i++)
        #pragma unroll
        for (int j = 0; j < 8; j++) acc[i][j] = 0ULL;

    for (int k0 = 0; k0 < DMODEL; k0 += 16) {
        #pragma unroll
        for (int it = 0; it < 8; it++) {
            int r = ty + it * 16;
            cs[tx][r] = (float)g_ctx[(size_t)(m0 + r) * DMODEL + k0 + tx];
            ws[tx][r] = wo[(size_t)(n0 + r) * DMODEL + k0 + tx];
        }
        __syncthreads();
        #pragma unroll
        for (int kk = 0; kk < 16; kk++) {
            ulonglong2 a01 = *(ulonglong2*)&cs[kk][ty * 8];
            ulonglong2 a23 = *(ulonglong2*)&cs[kk][ty * 8 + 4];
            float4 bA = *(float4*)&ws[kk][tx * 8];
            float4 bB = *(float4*)&ws[kk][tx * 8 + 4];
            unsigned long long a[4] = {a01.x, a01.y, a23.x, a23.y};
            unsigned long long bd[8];
            bd[0] = pack2(bA.x, bA.x); bd[1] = pack2(bA.y, bA.y);
            bd[2] = pack2(bA.z, bA.z); bd[3] = pack2(bA.w, bA.w);
            bd[4] = pack2(bB.x, bB.x); bd[5] = pack2(bB.y, bB.y);
            bd[6] = pack2(bB.z, bB.z); bd[7] = pack2(bB.w, bB.w);
            #pragma unroll
            for (int i = 0; i < 4; i++)
                #pragma unroll
                for (int j = 0; j < 8; j++)
                    ffma2(acc[i][j], a[i], bd[j]);
        }
        __syncthreads();
    }

    float bb[8];
    #pragma unroll
    for (int e = 0; e < 8; e++) bb[e] = bo[n0 + tx * 8 + e];

    #pragma unroll
    for (int mp = 0; mp < 4; mp++) {
        #pragma unroll
        for (int par = 0; par < 2; par++) {
            int m = m0 + ty * 8 + mp * 2 + par;
            float vals[8];
            #pragma unroll
            for (int j = 0; j < 8; j++) {
                float lo, hi; unpack2(acc[mp][j], lo, hi);
                float v = (par == 0) ? lo : hi;
                float r = floorf(((v + bb[j]) * 256.0f) * (1.0f / 128.0f));
                vals[j] = fminf(fmaxf(r, -128.0f), 127.0f);
            }
            float4* op = (float4*)&out[(size_t)m * DMODEL + n0 + tx * 8];
            op[0] = make_float4(vals[0], vals[1], vals[2], vals[3]);
            op[1] = make_float4(vals[4], vals[5], vals[6], vals[7]);
        }
    }
}

// ---------------------------------------------------------------------------
extern "C" void kernel_launch(void* const* d_in, const int* in_sizes, int n_in,
                              void* d_out, int out_size)
{
    const float* x  = (const float*)d_in[0];
    const float* wq = (const float*)d_in[1];
    const float* bq = (const float*)d_in[2];
    const float* wk = (const float*)d_in[3];
    const float* bk = (const float*)d_in[4];
    const float* wv = (const float*)d_in[5];
    const float* bv = (const float*)d_in[6];
    const float* wo = (const float*)d_in[7];
    const float* bo = (const float*)d_in[8];
    float* out = (float*)d_out;

    cudaFuncSetAttribute(attn_fused, cudaFuncAttributeMaxDynamicSharedMemorySize,
                         ATTN_SMEM_BYTES);

    proj_kernel<<<dim3(64, 3, 3), 256>>>(x, wq, bq, wk, bk, wv, bv);
    attn_fused<<<dim3(32, 24), 512, ATTN_SMEM_BYTES>>>();
    out_kernel<<<dim3(64, 3), 256>>>(wo, bo, out);
}

// round 10
// speedup vs baseline: 1.5677x; 1.2916x over previous
#include <cuda_runtime.h>
#include <cstdint>
#include <cstddef>

#define BATCH 4
#define SEQ 2048
#define DMODEL 384
#define NHEADS 6
#define HD 64
#define BH (BATCH*NHEADS)      /* 24 */

// ---------------- scratch (static device arrays; no cudaMalloc allowed) -------
__device__ __align__(16) int8_t g_Q  [(size_t)BH*SEQ*HD];        // [bh][n][d]
__device__ __align__(16) int8_t g_K  [(size_t)BH*SEQ*HD];        // [bh][n][d]
// V packed words: word (bh, nblk, d) = V[nblk*4 .. +3][d] bytes (packed along n)
__device__ __align__(16) int8_t g_Vp [(size_t)BH*(SEQ/4)*HD*4];  // [bh][nblk 512][d 64] int32 words
__device__ __align__(16) int8_t g_ctx[(size_t)BATCH*SEQ*DMODEL]; // [b][n][h*hd]

__device__ __forceinline__ int dp4a_us(unsigned a, int b, int c) {
    int d;
    asm("dp4a.u32.s32 %0, %1, %2, %3;" : "=r"(d) : "r"(a), "r"(b), "r"(c));
    return d;
}
__device__ __forceinline__ void ffma2(unsigned long long& d,
                                      unsigned long long a, unsigned long long b) {
    asm("fma.rn.f32x2 %0, %1, %2, %0;" : "+l"(d) : "l"(a), "l"(b));
}
__device__ __forceinline__ unsigned long long pack2(float lo, float hi) {
    unsigned long long p;
    asm("mov.b64 %0, {%1, %2};" : "=l"(p) : "f"(lo), "f"(hi));
    return p;
}
__device__ __forceinline__ void unpack2(unsigned long long p, float& lo, float& hi) {
    asm("mov.b64 {%0, %1}, %2;" : "=f"(lo), "=f"(hi) : "l"(p));
}
__device__ __forceinline__ int clamp_i8(int v) {
    return v < -128 ? -128 : (v > 127 ? 127 : v);
}
__device__ __forceinline__ unsigned pack_bytes(int v0, int v1, int v2, int v3) {
    return  ((unsigned)(unsigned char)(int8_t)v0)
          | (((unsigned)(unsigned char)(int8_t)v1) << 8)
          | (((unsigned)(unsigned char)(int8_t)v2) << 16)
          | (((unsigned)(unsigned char)(int8_t)v3) << 24);
}

// ---------------------------------------------------------------------------
// Kernel 1: QKV projection (f32x2 FMA, M-dim pairing).
// B columns split: thread covers n0+tx*4+j (j<4) and n0+64+tx*4+(j-4) (j>=4)
// -> conflict-free float4 LDS (stride 4).
// ---------------------------------------------------------------------------
__global__ void __launch_bounds__(256, 2) proj_kernel(
    const float* __restrict__ x,
    const float* __restrict__ wq, const float* __restrict__ bq,
    const float* __restrict__ wk, const float* __restrict__ bk,
    const float* __restrict__ wv, const float* __restrict__ bv)
{
    __shared__ float xs[16][132];      // [kk][m]
    __shared__ float ws[16][132];      // [kk][n]
    __shared__ int8_t vq[128][132];    // V transpose staging (z==2)

    const int z = blockIdx.z;
    const float* w    = (z == 0) ? wq : ((z == 1) ? wk : wv);
    const float* bias = (z == 0) ? bq : ((z == 1) ? bk : bv);
    const int m0 = blockIdx.x * 128;
    const int n0 = blockIdx.y * 128;
    const int tid = threadIdx.x, tx = tid & 15, ty = tid >> 4;

    unsigned long long acc[4][8];      // [m-pair][n]
    #pragma unroll
    for (int i = 0; i < 4; i++)
        #pragma unroll
        for (int j = 0; j < 8; j++) acc[i][j] = 0ULL;

    for (int k0 = 0; k0 < DMODEL; k0 += 16) {
        #pragma unroll
        for (int it = 0; it < 8; it++) {
            int r = ty + it * 16;
            xs[tx][r] = x[(size_t)(m0 + r) * DMODEL + k0 + tx];
            ws[tx][r] = w[(size_t)(n0 + r) * DMODEL + k0 + tx];
        }
        __syncthreads();
        #pragma unroll
        for (int kk = 0; kk < 16; kk++) {
            ulonglong2 a01 = *(ulonglong2*)&xs[kk][ty * 8];
            ulonglong2 a23 = *(ulonglong2*)&xs[kk][ty * 8 + 4];
            float4 bA = *(float4*)&ws[kk][tx * 4];        // cols tx*4..+3
            float4 bB = *(float4*)&ws[kk][64 + tx * 4];   // cols 64+tx*4..+3
            unsigned long long a[4] = {a01.x, a01.y, a23.x, a23.y};
            unsigned long long bd[8];
            bd[0] = pack2(bA.x, bA.x); bd[1] = pack2(bA.y, bA.y);
            bd[2] = pack2(bA.z, bA.z); bd[3] = pack2(bA.w, bA.w);
            bd[4] = pack2(bB.x, bB.x); bd[5] = pack2(bB.y, bB.y);
            bd[6] = pack2(bB.z, bB.z); bd[7] = pack2(bB.w, bB.w);
            #pragma unroll
            for (int i = 0; i < 4; i++)
                #pragma unroll
                for (int j = 0; j < 8; j++)
                    ffma2(acc[i][j], a[i], bd[j]);
        }
        __syncthreads();
    }

    float bb[8];
    #pragma unroll
    for (int e = 0; e < 4; e++) bb[e] = bias[n0 + tx * 4 + e];
    #pragma unroll
    for (int e = 4; e < 8; e++) bb[e] = bias[n0 + 64 + tx * 4 + (e - 4)];

    if (z < 2) {
        int8_t* dst = (z == 0) ? g_Q : g_K;
        const int hA = n0 >> 6, hB = hA + 1;   // n0 multiple of 128
        #pragma unroll
        for (int mp = 0; mp < 4; mp++) {
            #pragma unroll
            for (int par = 0; par < 2; par++) {
                int m = m0 + ty * 8 + mp * 2 + par;
                int b_ = m >> 11, n = m & 2047;
                unsigned wA = 0, wB = 0;
                #pragma unroll
                for (int j = 0; j < 8; j++) {
                    float lo, hi; unpack2(acc[mp][j], lo, hi);
                    float v = (par == 0) ? lo : hi;
                    float r = floorf(((v + bb[j]) * 16384.0f) * (1.0f / 256.0f));
                    r = fminf(fmaxf(r, -128.0f), 127.0f);
                    unsigned u = (unsigned)(unsigned char)(int8_t)(int)r;
                    if (j < 4) wA |= u << (8 * j);
                    else       wB |= u << (8 * (j - 4));
                }
                ((int*)dst)[((size_t)(b_ * NHEADS + hA) * SEQ + n) * 16 + tx] = (int)wA;
                ((int*)dst)[((size_t)(b_ * NHEADS + hB) * SEQ + n) * 16 + tx] = (int)wB;
            }
        }
    } else {
        #pragma unroll
        for (int mp = 0; mp < 4; mp++) {
            #pragma unroll
            for (int j = 0; j < 8; j++) {
                float lo, hi; unpack2(acc[mp][j], lo, hi);
                float r0 = floorf(((lo + bb[j]) * 16384.0f) * (1.0f / 256.0f));
                r0 = fminf(fmaxf(r0, -128.0f), 127.0f);
                float r1 = floorf(((hi + bb[j]) * 16384.0f) * (1.0f / 256.0f));
                r1 = fminf(fmaxf(r1, -128.0f), 127.0f);
                int col = (j < 4) ? (tx * 4 + j) : (64 + tx * 4 + (j - 4));
                vq[col][ty * 8 + mp * 2]     = (int8_t)(int)r0;
                vq[col][ty * 8 + mp * 2 + 1] = (int8_t)(int)r1;
            }
        }
        __syncthreads();
        int b_ = m0 >> 11;
        int nloc = m0 & 2047;
        #pragma unroll
        for (int it = 0; it < 16; it++) {
            int idx = tid + it * 256;              // 0..4095
            int col = idx & 127;                   // feature col (fast -> coalesced d)
            int j4  = idx >> 7;                    // nblk within tile (0..31)
            int word = *(int*)&vq[col][j4 * 4];
            int cg = n0 + col, h = cg >> 6, d = cg & 63;
            size_t nblk = (size_t)((nloc >> 2) + j4);
            ((int*)g_Vp)[((size_t)(b_ * NHEADS + h) * (SEQ/4) + nblk) * HD + d] = word;
        }
    }
}

// ---------------------------------------------------------------------------
// Kernel 2: fused attention, 512 threads. One block = (bh, 64-q strip).
// Phase 1: logits, 64q x 256key tiles, conflict-free stride-4 B loads
// Phase 2: ITA scan, 8x-parallel exact decomposition (passes A-D)
// Phase 2b: logits -> attn bytes in place (interleaved, conflict-free)
// Phase 3: attn @ V, k-split x4, stride-4 V loads, smem reduction
// ---------------------------------------------------------------------------
#define SW 516                                    /* padded S row (words) */
#define KP 260                                    /* K tile row pad (words) */
#define VPAD 68                                   /* V tile row pad (words) */
#define U_INTS 16384                              /* union: kb / vb / red / scan */
#define SCAN_P 130                                /* scan scratch row pad */
#define ATTN_SMEM_INTS (64*SW + 16*68 + U_INTS + 128)
#define ATTN_SMEM_BYTES (ATTN_SMEM_INTS * 4)

extern __shared__ int smem_raw[];

__global__ void __launch_bounds__(512) attn_fused()
{
    int* SM = smem_raw;
    unsigned* S = (unsigned*)SM;                  // [64][SW]
    int* qs    = SM + 64 * SW;                    // [16][68] transposed Q
    int* U     = qs + 16 * 68;                    // union region (16384 ints)
    int* gmaxs = U + U_INTS;                      // [64]
    int* invs  = gmaxs + 64;                      // [64]

    const int bh = blockIdx.y;
    const int q0 = blockIdx.x * 64;
    const int tid = threadIdx.x;
    const int lane = tid & 31, warp = tid >> 5;   // 16 warps

    const int* Qw = (const int*)g_Q + (size_t)bh * SEQ * (HD/4) + (size_t)q0 * (HD/4);
    const int* Kw = (const int*)g_K + (size_t)bh * SEQ * (HD/4);
    const int* Vw = (const int*)g_Vp + (size_t)bh * (SEQ/4) * HD;

    // ---- Q transposed: qs[kk][qrow] (1024 words) ----
    #pragma unroll
    for (int it = 0; it < 2; it++) {
        int idx = tid + it * 512;
        qs[(idx & 15) * 68 + (idx >> 4)] = Qw[idx];
    }
    // ---- prefetch K tile 0 (256 rows x 16 words = 4096) ----
    int pre[8];
    #pragma unroll
    for (int it = 0; it < 8; it++) pre[it] = Kw[tid + it * 512];
    #pragma unroll
    for (int it = 0; it < 8; it++) {
        int idx = tid + it * 512;
        U[(idx & 15) * KP + (idx >> 4)] = pre[it];
    }
    __syncthreads();

    // -------- Phase 1: logits, 8 tiles of 256 keys --------
    // thread (warp, lane) covers q rows warp*4..+3, key words: t*64+lane, t*64+32+lane
    for (int t = 0; t < 8; t++) {
        int cur = t & 1;
        if (t + 1 < 8) {
            const int* Kt = Kw + (size_t)(t + 1) * 4096;
            #pragma unroll
            for (int it = 0; it < 8; it++) pre[it] = Kt[tid + it * 512];
        }
        const int* kbc = U + cur * 16 * KP;
        int acc[4][8];
        #pragma unroll
        for (int i = 0; i < 4; i++)
            #pragma unroll
            for (int j = 0; j < 8; j++) acc[i][j] = 0;
        #pragma unroll
        for (int kk = 0; kk < 16; kk++) {
            int4 av = *(const int4*)&qs[kk * 68 + warp * 4];        // broadcast
            int4 b0 = *(const int4*)&kbc[kk * KP + lane * 4];       // keys lane*4..+3 (stride 4, CF)
            int4 b1 = *(const int4*)&kbc[kk * KP + 128 + lane * 4]; // keys 128+lane*4..+3
            int a[4] = {av.x, av.y, av.z, av.w};
            int b[8] = {b0.x, b0.y, b0.z, b0.w, b1.x, b1.y, b1.z, b1.w};
            #pragma unroll
            for (int i = 0; i < 4; i++)
                #pragma unroll
                for (int j = 0; j < 8; j++)
                    acc[i][j] = __dp4a(a[i], b[j], acc[i][j]);
        }
        #pragma unroll
        for (int i = 0; i < 4; i++) {
            unsigned w0 = pack_bytes(clamp_i8((acc[i][0]*5) >> 12), clamp_i8((acc[i][1]*5) >> 12),
                                     clamp_i8((acc[i][2]*5) >> 12), clamp_i8((acc[i][3]*5) >> 12));
            unsigned w1 = pack_bytes(clamp_i8((acc[i][4]*5) >> 12), clamp_i8((acc[i][5]*5) >> 12),
                                     clamp_i8((acc[i][6]*5) >> 12), clamp_i8((acc[i][7]*5) >> 12));
            S[(warp * 4 + i) * SW + t * 64 + lane]      = w0;
            S[(warp * 4 + i) * SW + t * 64 + 32 + lane] = w1;
        }
        __syncthreads();
        if (t + 1 < 8) {
            int nb = (t + 1) & 1;
            #pragma unroll
            for (int it = 0; it < 8; it++) {
                int idx = tid + it * 512;
                U[nb * 16 * KP + (idx & 15) * KP + (idx >> 4)] = pre[it];
            }
            __syncthreads();
        }
    }

    // -------- Phase 2: ITA scan, exact 8x-parallel decomposition --------
    // Pass A: per-chunk maxima (chunk = 16 keys = int4 of S words)
    {
        int row = tid >> 3, seg = tid & 7;
        const int* srow = (const int*)&S[row * SW];
        #pragma unroll
        for (int cc = 0; cc < 16; cc++) {
            int j = cc * 8 + seg;                  // interleaved -> conflict-free
            int4 wv = *(const int4*)&srow[j * 4];
            int mw = __vmaxs4(__vmaxs4(wv.x, wv.y), __vmaxs4(wv.z, wv.w));
            int cmax = -128;
            #pragma unroll
            for (int b = 0; b < 4; b++) {
                int v = (int)(int8_t)((unsigned)mw >> (8 * b));
                cmax = max(cmax, v);
            }
            U[row * SCAN_P + j] = cmax;
        }
    }
    __syncthreads();
    // Pass B: running gmax per row (sequential, 128 cheap steps)
    if (tid < 64) {
        int g = -128;
        int* urow = U + tid * SCAN_P;
        for (int j = 0; j < 128; j++) {
            int c = urow[j];
            if (c > g) g = c;
            urow[j] = (int)((unsigned)(g + 128) << 16);   // pack gmax, e-field 0
        }
        gmaxs[tid] = g;
    }
    __syncthreads();
    // Pass C: e_j for each chunk given gmax_j (parallel)
    {
        int row = tid >> 3, seg = tid & 7;
        const int* srow = (const int*)&S[row * SW];
        int* urow = U + row * SCAN_P;
        #pragma unroll
        for (int cc = 0; cc < 16; cc++) {
            int j = cc * 8 + seg;
            unsigned pk = (unsigned)urow[j];
            int g = (int)(pk >> 16) - 128;
            int4 wv = *(const int4*)&srow[j * 4];
            int words[4] = {wv.x, wv.y, wv.z, wv.w};
            int es = 0;
            #pragma unroll
            for (int jw = 0; jw < 4; jw++) {
                int wvv = words[jw];
                #pragma unroll
                for (int b = 0; b < 4; b++) {
                    int xv = (int)(int8_t)((unsigned)wvv >> (8 * b));
                    int df = g - xv;               // >= 0
                    es += (df < 9) ? (256 >> df) : 0;
                }
            }
            urow[j] = (int)(pk | (unsigned)es);    // es <= 4096, fits 16 bits
        }
    }
    __syncthreads();
    // Pass D: exact sequential combine ps = (ps >> delta) + e  (128 cheap steps)
    if (tid < 64) {
        const int* urow = U + tid * SCAN_P;
        int ps = 0, gprev = -128;
        for (int j = 0; j < 128; j++) {
            unsigned pk = (unsigned)urow[j];
            int g = (int)(pk >> 16) - 128;
            int e = (int)(pk & 0xFFFFu);
            int sh = g - gprev;                    // >= 0
            ps = (sh < 31) ? (ps >> sh) : 0;
            ps += e;
            gprev = g;
        }
        invs[tid] = 65280 / ps;                    // exact == floor(65280.0/ps)
    }
    __syncthreads();

    // ---- prefetch V tile 0 while doing phase 2b ----
    #pragma unroll
    for (int it = 0; it < 8; it++) pre[it] = Vw[tid + it * 512];

    // -------- Phase 2b: logits -> attn bytes, in place (interleaved) --------
    {
        int q = tid >> 3, seg = tid & 7;
        int gm = gmaxs[q];
        unsigned inv = (unsigned)invs[q];
        for (int c = 0; c < 64; c++) {
            int w = c * 8 + seg;                   // conflict-free
            unsigned xw = S[q * SW + w];
            unsigned o = 0;
            #pragma unroll
            for (int b = 0; b < 4; b++) {
                int xv = (int)(int8_t)(xw >> (8 * b));
                int df = gm - xv;
                if (df > 31) df = 31;
                o |= (inv >> df) << (8 * b);
            }
            S[q * SW + w] = o;
        }
    }
    __syncthreads();
    #pragma unroll
    for (int it = 0; it < 8; it++) {
        int idx = tid + it * 512;
        U[(idx >> 6) * VPAD + (idx & 63)] = pre[it];   // vb[kwl][d]
    }
    __syncthreads();

    // -------- Phase 3: attn @ V, 8 tiles of 64 kwords, k-split x4 --------
    const int wq = warp & 3;              // q quarter
    const int wk = warp >> 2;             // k quarter
    const int lq = lane >> 3;             // q sub (4)
    const int ld = lane & 7;              // d group (8)
    const int qr0 = wq * 16 + lq * 4;     // thread's first q row

    int acc3[4][8];
    #pragma unroll
    for (int i = 0; i < 4; i++)
        #pragma unroll
        for (int j = 0; j < 8; j++) acc3[i][j] = 0;

    for (int t = 0; t < 8; t++) {
        int cur = t & 1;
        if (t + 1 < 8) {
            const int* Vt = Vw + (size_t)(t + 1) * 4096;
            #pragma unroll
            for (int it = 0; it < 8; it++) pre[it] = Vt[tid + it * 512];
        }
        const int* vbc = U + cur * 64 * VPAD;
        #pragma unroll
        for (int kki = 0; kki < 16; kki++) {
            int kwl = wk * 16 + kki;
            unsigned a[4];
            #pragma unroll
            for (int i = 0; i < 4; i++)
                a[i] = S[(qr0 + i) * SW + t * 64 + kwl];           // 4-distinct broadcast
            int4 b0 = *(const int4*)&vbc[kwl * VPAD + ld * 4];      // d ld*4..+3 (CF)
            int4 b1 = *(const int4*)&vbc[kwl * VPAD + 32 + ld * 4]; // d 32+ld*4..+3
            int b[8] = {b0.x, b0.y, b0.z, b0.w, b1.x, b1.y, b1.z, b1.w};
            #pragma unroll
            for (int i = 0; i < 4; i++)
                #pragma unroll
                for (int j = 0; j < 8; j++)
                    acc3[i][j] = dp4a_us(a[i], b[j], acc3[i][j]);
        }
        __syncthreads();
        if (t + 1 < 8) {
            int nb = (t + 1) & 1;
            #pragma unroll
            for (int it = 0; it < 8; it++) {
                int idx = tid + it * 512;
                U[nb * 64 * VPAD + (idx >> 6) * VPAD + (idx & 63)] = pre[it];
            }
            __syncthreads();
        }
    }

    // ---- reduction across the 4 k-groups via union region ----
    __syncthreads();                       // all vb reads done; reuse U as red[4][64][64]
    #pragma unroll
    for (int i = 0; i < 4; i++) {
        *(int4*)&U[wk * 4096 + (qr0 + i) * 64 + ld * 4]      = make_int4(acc3[i][0], acc3[i][1], acc3[i][2], acc3[i][3]);
        *(int4*)&U[wk * 4096 + (qr0 + i) * 64 + 32 + ld * 4] = make_int4(acc3[i][4], acc3[i][5], acc3[i][6], acc3[i][7]);
    }
    __syncthreads();

    {
        const int b_ = bh / NHEADS, h = bh % NHEADS;
        int q = tid >> 3;
        int d0 = (tid & 7) * 8;
        int4 s0 = make_int4(0,0,0,0), s1 = make_int4(0,0,0,0);
        #pragma unroll
        for (int g = 0; g < 4; g++) {
            int4 a0 = *(const int4*)&U[g * 4096 + q * 64 + d0];
            int4 a1 = *(const int4*)&U[g * 4096 + q * 64 + d0 + 4];
            s0.x += a0.x; s0.y += a0.y; s0.z += a0.z; s0.w += a0.w;
            s1.x += a1.x; s1.y += a1.y; s1.z += a1.z; s1.w += a1.w;
        }
        unsigned lo = pack_bytes(clamp_i8(s0.x >> 8), clamp_i8(s0.y >> 8),
                                 clamp_i8(s0.z >> 8), clamp_i8(s0.w >> 8));
        unsigned hi = pack_bytes(clamp_i8(s1.x >> 8), clamp_i8(s1.y >> 8),
                                 clamp_i8(s1.z >> 8), clamp_i8(s1.w >> 8));
        *(int2*)(g_ctx + ((size_t)(b_ * SEQ + q0 + q)) * DMODEL + h * HD + d0) = make_int2((int)lo, (int)hi);
    }
}

// ---------------------------------------------------------------------------
// Kernel 3: out = requantize(ctx @ wo^T + bo, 256, 7), f32x2 + split B cols
// ---------------------------------------------------------------------------
__global__ void __launch_bounds__(256, 2) out_kernel(
    const float* __restrict__ wo, const float* __restrict__ bo,
    float* __restrict__ out)
{
    __shared__ float cs[16][132];
    __shared__ float ws[16][132];

    const int m0 = blockIdx.x * 128;
    const int n0 = blockIdx.y * 128;
    const int tid = threadIdx.x, tx = tid & 15, ty = tid >> 4;

    unsigned long long acc[4][8];
    #pragma unroll
    for (int i = 0; i < 4; i++)
        #pragma unroll
        for (int j = 0; j < 8; j++) acc[i][j] = 0ULL;

    for (int k0 = 0; k0 < DMODEL; k0 += 16) {
        #pragma unroll
        for (int it = 0; it < 8; it++) {
            int r = ty + it * 16;
            cs[tx][r] = (float)g_ctx[(size_t)(m0 + r) * DMODEL + k0 + tx];
            ws[tx][r] = wo[(size_t)(n0 + r) * DMODEL + k0 + tx];
        }
        __syncthreads();
        #pragma unroll
        for (int kk = 0; kk < 16; kk++) {
            ulonglong2 a01 = *(ulonglong2*)&cs[kk][ty * 8];
            ulonglong2 a23 = *(ulonglong2*)&cs[kk][ty * 8 + 4];
            float4 bA = *(float4*)&ws[kk][tx * 4];
            float4 bB = *(float4*)&ws[kk][64 + tx * 4];
            unsigned long long a[4] = {a01.x, a01.y, a23.x, a23.y};
            unsigned long long bd[8];
            bd[0] = pack2(bA.x, bA.x); bd[1] = pack2(bA.y, bA.y);
            bd[2] = pack2(bA.z, bA.z); bd[3] = pack2(bA.w, bA.w);
            bd[4] = pack2(bB.x, bB.x); bd[5] = pack2(bB.y, bB.y);
            bd[6] = pack2(bB.z, bB.z); bd[7] = pack2(bB.w, bB.w);
            #pragma unroll
            for (int i = 0; i < 4; i++)
                #pragma unroll
                for (int j = 0; j < 8; j++)
                    ffma2(acc[i][j], a[i], bd[j]);
        }
        __syncthreads();
    }

    float bb[8];
    #pragma unroll
    for (int e = 0; e < 4; e++) bb[e] = bo[n0 + tx * 4 + e];
    #pragma unroll
    for (int e = 4; e < 8; e++) bb[e] = bo[n0 + 64 + tx * 4 + (e - 4)];

    #pragma unroll
    for (int mp = 0; mp < 4; mp++) {
        #pragma unroll
        for (int par = 0; par < 2; par++) {
            int m = m0 + ty * 8 + mp * 2 + par;
            float vals[8];
            #pragma unroll
            for (int j = 0; j < 8; j++) {
                float lo, hi; unpack2(acc[mp][j], lo, hi);
                float v = (par == 0) ? lo : hi;
                float r = floorf(((v + bb[j]) * 256.0f) * (1.0f / 128.0f));
                vals[j] = fminf(fmaxf(r, -128.0f), 127.0f);
            }
            *(float4*)&out[(size_t)m * DMODEL + n0 + tx * 4] =
                make_float4(vals[0], vals[1], vals[2], vals[3]);
            *(float4*)&out[(size_t)m * DMODEL + n0 + 64 + tx * 4] =
                make_float4(vals[4], vals[5], vals[6], vals[7]);
        }
    }
}

// ---------------------------------------------------------------------------
extern "C" void kernel_launch(void* const* d_in, const int* in_sizes, int n_in,
                              void* d_out, int out_size)
{
    const float* x  = (const float*)d_in[0];
    const float* wq = (const float*)d_in[1];
    const float* bq = (const float*)d_in[2];
    const float* wk = (const float*)d_in[3];
    const float* bk = (const float*)d_in[4];
    const float* wv = (const float*)d_in[5];
    const float* bv = (const float*)d_in[6];
    const float* wo = (const float*)d_in[7];
    const float* bo = (const float*)d_in[8];
    float* out = (float*)d_out;

    cudaFuncSetAttribute(attn_fused, cudaFuncAttributeMaxDynamicSharedMemorySize,
                         ATTN_SMEM_BYTES);

    proj_kernel<<<dim3(64, 3, 3), 256>>>(x, wq, bq, wk, bk, wv, bv);
    attn_fused<<<dim3(32, 24), 512, ATTN_SMEM_BYTES>>>();
    out_kernel<<<dim3(64, 3), 256>>>(wo, bo, out);
}

// round 11
// speedup vs baseline: 1.6808x; 1.0721x over previous
#include <cuda_runtime.h>
#include <cstdint>
#include <cstddef>

#define BATCH 4
#define SEQ 2048
#define DMODEL 384
#define NHEADS 6
#define HD 64
#define BH (BATCH*NHEADS)      /* 24 */

// ---------------- scratch (static device arrays; no cudaMalloc allowed) -------
__device__ __align__(16) int8_t g_Q  [(size_t)BH*SEQ*HD];        // [bh][n][d]
__device__ __align__(16) int8_t g_K  [(size_t)BH*SEQ*HD];        // [bh][n][d]
// V packed words: word (bh, nblk, d) = V[nblk*4 .. +3][d] bytes (packed along n)
__device__ __align__(16) int8_t g_Vp [(size_t)BH*(SEQ/4)*HD*4];  // [bh][nblk 512][d 64] int32 words
__device__ __align__(16) int8_t g_ctx[(size_t)BATCH*SEQ*DMODEL]; // [b][n][h*hd]

__device__ __forceinline__ int dp4a_us(unsigned a, int b, int c) {
    int d;
    asm("dp4a.u32.s32 %0, %1, %2, %3;" : "=r"(d) : "r"(a), "r"(b), "r"(c));
    return d;
}
__device__ __forceinline__ void ffma2(unsigned long long& d,
                                      unsigned long long a, unsigned long long b) {
    asm("fma.rn.f32x2 %0, %1, %2, %0;" : "+l"(d) : "l"(a), "l"(b));
}
__device__ __forceinline__ unsigned long long pack2(float lo, float hi) {
    unsigned long long p;
    asm("mov.b64 %0, {%1, %2};" : "=l"(p) : "f"(lo), "f"(hi));
    return p;
}
__device__ __forceinline__ void unpack2(unsigned long long p, float& lo, float& hi) {
    asm("mov.b64 {%0, %1}, %2;" : "=f"(lo), "=f"(hi) : "l"(p));
}
__device__ __forceinline__ int clamp_i8(int v) {
    return v < -128 ? -128 : (v > 127 ? 127 : v);
}
__device__ __forceinline__ unsigned pack_bytes(int v0, int v1, int v2, int v3) {
    return  ((unsigned)(unsigned char)(int8_t)v0)
          | (((unsigned)(unsigned char)(int8_t)v1) << 8)
          | (((unsigned)(unsigned char)(int8_t)v2) << 16)
          | (((unsigned)(unsigned char)(int8_t)v3) << 24);
}

// ---------------------------------------------------------------------------
// Kernel 1: QKV projection (f32x2 FMA, M-dim pairing, stride-4 CF B loads).
// Unchanged from R9 (verified rel_err 0).
// ---------------------------------------------------------------------------
__global__ void __launch_bounds__(256, 2) proj_kernel(
    const float* __restrict__ x,
    const float* __restrict__ wq, const float* __restrict__ bq,
    const float* __restrict__ wk, const float* __restrict__ bk,
    const float* __restrict__ wv, const float* __restrict__ bv)
{
    __shared__ float xs[16][132];      // [kk][m]
    __shared__ float ws[16][132];      // [kk][n]
    __shared__ int8_t vq[128][132];    // V transpose staging (z==2)

    const int z = blockIdx.z;
    const float* w    = (z == 0) ? wq : ((z == 1) ? wk : wv);
    const float* bias = (z == 0) ? bq : ((z == 1) ? bk : bv);
    const int m0 = blockIdx.x * 128;
    const int n0 = blockIdx.y * 128;
    const int tid = threadIdx.x, tx = tid & 15, ty = tid >> 4;

    unsigned long long acc[4][8];      // [m-pair][n]
    #pragma unroll
    for (int i = 0; i < 4; i++)
        #pragma unroll
        for (int j = 0; j < 8; j++) acc[i][j] = 0ULL;

    for (int k0 = 0; k0 < DMODEL; k0 += 16) {
        #pragma unroll
        for (int it = 0; it < 8; it++) {
            int r = ty + it * 16;
            xs[tx][r] = x[(size_t)(m0 + r) * DMODEL + k0 + tx];
            ws[tx][r] = w[(size_t)(n0 + r) * DMODEL + k0 + tx];
        }
        __syncthreads();
        #pragma unroll
        for (int kk = 0; kk < 16; kk++) {
            ulonglong2 a01 = *(ulonglong2*)&xs[kk][ty * 8];
            ulonglong2 a23 = *(ulonglong2*)&xs[kk][ty * 8 + 4];
            float4 bA = *(float4*)&ws[kk][tx * 4];        // cols tx*4..+3
            float4 bB = *(float4*)&ws[kk][64 + tx * 4];   // cols 64+tx*4..+3
            unsigned long long a[4] = {a01.x, a01.y, a23.x, a23.y};
            unsigned long long bd[8];
            bd[0] = pack2(bA.x, bA.x); bd[1] = pack2(bA.y, bA.y);
            bd[2] = pack2(bA.z, bA.z); bd[3] = pack2(bA.w, bA.w);
            bd[4] = pack2(bB.x, bB.x); bd[5] = pack2(bB.y, bB.y);
            bd[6] = pack2(bB.z, bB.z); bd[7] = pack2(bB.w, bB.w);
            #pragma unroll
            for (int i = 0; i < 4; i++)
                #pragma unroll
                for (int j = 0; j < 8; j++)
                    ffma2(acc[i][j], a[i], bd[j]);
        }
        __syncthreads();
    }

    float bb[8];
    #pragma unroll
    for (int e = 0; e < 4; e++) bb[e] = bias[n0 + tx * 4 + e];
    #pragma unroll
    for (int e = 4; e < 8; e++) bb[e] = bias[n0 + 64 + tx * 4 + (e - 4)];

    if (z < 2) {
        int8_t* dst = (z == 0) ? g_Q : g_K;
        const int hA = n0 >> 6, hB = hA + 1;   // n0 multiple of 128
        #pragma unroll
        for (int mp = 0; mp < 4; mp++) {
            #pragma unroll
            for (int par = 0; par < 2; par++) {
                int m = m0 + ty * 8 + mp * 2 + par;
                int b_ = m >> 11, n = m & 2047;
                unsigned wA = 0, wB = 0;
                #pragma unroll
                for (int j = 0; j < 8; j++) {
                    float lo, hi; unpack2(acc[mp][j], lo, hi);
                    float v = (par == 0) ? lo : hi;
                    float r = floorf(((v + bb[j]) * 16384.0f) * (1.0f / 256.0f));
                    r = fminf(fmaxf(r, -128.0f), 127.0f);
                    unsigned u = (unsigned)(unsigned char)(int8_t)(int)r;
                    if (j < 4) wA |= u << (8 * j);
                    else       wB |= u << (8 * (j - 4));
                }
                ((int*)dst)[((size_t)(b_ * NHEADS + hA) * SEQ + n) * 16 + tx] = (int)wA;
                ((int*)dst)[((size_t)(b_ * NHEADS + hB) * SEQ + n) * 16 + tx] = (int)wB;
            }
        }
    } else {
        #pragma unroll
        for (int mp = 0; mp < 4; mp++) {
            #pragma unroll
            for (int j = 0; j < 8; j++) {
                float lo, hi; unpack2(acc[mp][j], lo, hi);
                float r0 = floorf(((lo + bb[j]) * 16384.0f) * (1.0f / 256.0f));
                r0 = fminf(fmaxf(r0, -128.0f), 127.0f);
                float r1 = floorf(((hi + bb[j]) * 16384.0f) * (1.0f / 256.0f));
                r1 = fminf(fmaxf(r1, -128.0f), 127.0f);
                int col = (j < 4) ? (tx * 4 + j) : (64 + tx * 4 + (j - 4));
                vq[col][ty * 8 + mp * 2]     = (int8_t)(int)r0;
                vq[col][ty * 8 + mp * 2 + 1] = (int8_t)(int)r1;
            }
        }
        __syncthreads();
        int b_ = m0 >> 11;
        int nloc = m0 & 2047;
        #pragma unroll
        for (int it = 0; it < 16; it++) {
            int idx = tid + it * 256;              // 0..4095
            int col = idx & 127;
            int j4  = idx >> 7;
            int word = *(int*)&vq[col][j4 * 4];
            int cg = n0 + col, h = cg >> 6, d = cg & 63;
            size_t nblk = (size_t)((nloc >> 2) + j4);
            ((int*)g_Vp)[((size_t)(b_ * NHEADS + h) * (SEQ/4) + nblk) * HD + d] = word;
        }
    }
}

// ---------------------------------------------------------------------------
// Kernel 2: fused attention, 256 threads, 32-q strips -> 2 CTAs/SM.
// Phase 1: logits, 32q x 256key tiles (dp4a, stride-4 CF B loads)
// Phase 2: ITA scan, exact 8x-parallel decomposition (passes A-D)
// Phase 2b: logits -> attn bytes in place (interleaved, CF)
// Phase 3: attn @ V, k-split x4, stride-4 V loads, smem reduction
// ---------------------------------------------------------------------------
#define QROWS 32
#define SW 516                                    /* padded S row (words) */
#define QSP 36                                    /* qs row pad */
#define KP 260                                    /* K tile row pad (words) */
#define VPAD 68                                   /* V tile row pad (words) */
#define U_INTS 8704                               /* union: kb / vb / red / scan */
#define SCAN_P 130                                /* scan scratch row pad */
#define ATTN_SMEM_INTS (QROWS*SW + 16*QSP + U_INTS + 96)
#define ATTN_SMEM_BYTES (ATTN_SMEM_INTS * 4)      /* ~103.7 KB -> 2 CTAs/SM */

extern __shared__ int smem_raw[];

__global__ void __launch_bounds__(256, 2) attn_fused()
{
    int* SM = smem_raw;
    unsigned* S = (unsigned*)SM;                  // [32][SW]
    int* qs    = SM + QROWS * SW;                 // [16][QSP] transposed Q
    int* U     = qs + 16 * QSP;                   // union region (8704 ints)
    int* gmaxs = U + U_INTS;                      // [32]
    int* invs  = gmaxs + 32;                      // [32]

    const int bh = blockIdx.y;
    const int q0 = blockIdx.x * QROWS;
    const int tid = threadIdx.x;
    const int lane = tid & 31, warp = tid >> 5;   // 8 warps

    const int* Qw = (const int*)g_Q + (size_t)bh * SEQ * (HD/4) + (size_t)q0 * (HD/4);
    const int* Kw = (const int*)g_K + (size_t)bh * SEQ * (HD/4);
    const int* Vw = (const int*)g_Vp + (size_t)bh * (SEQ/4) * HD;

    // ---- Q transposed: qs[kk][qrow] (512 words) ----
    #pragma unroll
    for (int it = 0; it < 2; it++) {
        int idx = tid + it * 256;
        qs[(idx & 15) * QSP + (idx >> 4)] = Qw[idx];
    }
    // ---- prefetch K tile 0 (256 rows x 16 words = 4096 ints) ----
    int pre[16];
    #pragma unroll
    for (int it = 0; it < 16; it++) pre[it] = Kw[tid + it * 256];
    #pragma unroll
    for (int it = 0; it < 16; it++) {
        int idx = tid + it * 256;
        U[(idx & 15) * KP + (idx >> 4)] = pre[it];
    }
    __syncthreads();

    // -------- Phase 1: logits, 8 tiles of 256 keys --------
    // warp covers q rows warp*4..+3 (broadcast); lane covers keys lane*4..+3, 128+lane*4..+3
    for (int t = 0; t < 8; t++) {
        int cur = t & 1;
        if (t + 1 < 8) {
            const int* Kt = Kw + (size_t)(t + 1) * 4096;
            #pragma unroll
            for (int it = 0; it < 16; it++) pre[it] = Kt[tid + it * 256];
        }
        const int* kbc = U + cur * 16 * KP;
        int acc[4][8];
        #pragma unroll
        for (int i = 0; i < 4; i++)
            #pragma unroll
            for (int j = 0; j < 8; j++) acc[i][j] = 0;
        #pragma unroll
        for (int kk = 0; kk < 16; kk++) {
            int4 av = *(const int4*)&qs[kk * QSP + warp * 4];        // broadcast
            int4 b0 = *(const int4*)&kbc[kk * KP + lane * 4];        // CF stride 4
            int4 b1 = *(const int4*)&kbc[kk * KP + 128 + lane * 4];
            int a[4] = {av.x, av.y, av.z, av.w};
            int b[8] = {b0.x, b0.y, b0.z, b0.w, b1.x, b1.y, b1.z, b1.w};
            #pragma unroll
            for (int i = 0; i < 4; i++)
                #pragma unroll
                for (int j = 0; j < 8; j++)
                    acc[i][j] = __dp4a(a[i], b[j], acc[i][j]);
        }
        #pragma unroll
        for (int i = 0; i < 4; i++) {
            unsigned w0 = pack_bytes(clamp_i8((acc[i][0]*5) >> 12), clamp_i8((acc[i][1]*5) >> 12),
                                     clamp_i8((acc[i][2]*5) >> 12), clamp_i8((acc[i][3]*5) >> 12));
            unsigned w1 = pack_bytes(clamp_i8((acc[i][4]*5) >> 12), clamp_i8((acc[i][5]*5) >> 12),
                                     clamp_i8((acc[i][6]*5) >> 12), clamp_i8((acc[i][7]*5) >> 12));
            S[(warp * 4 + i) * SW + t * 64 + lane]      = w0;
            S[(warp * 4 + i) * SW + t * 64 + 32 + lane] = w1;
        }
        __syncthreads();
        if (t + 1 < 8) {
            int nb = (t + 1) & 1;
            #pragma unroll
            for (int it = 0; it < 16; it++) {
                int idx = tid + it * 256;
                U[nb * 16 * KP + (idx & 15) * KP + (idx >> 4)] = pre[it];
            }
            __syncthreads();
        }
    }

    // -------- Phase 2: ITA scan, exact 8x-parallel decomposition --------
    // Pass A: per-chunk maxima (chunk = 16 keys). 8 threads per row, interleaved.
    {
        int row = tid >> 3, seg = tid & 7;        // row 0..31
        const int* srow = (const int*)&S[row * SW];
        #pragma unroll
        for (int cc = 0; cc < 16; cc++) {
            int j = cc * 8 + seg;                 // conflict-free
            int4 wv = *(const int4*)&srow[j * 4];
            int mw = __vmaxs4(__vmaxs4(wv.x, wv.y), __vmaxs4(wv.z, wv.w));
            int cmax = -128;
            #pragma unroll
            for (int b = 0; b < 4; b++) {
                int v = (int)(int8_t)((unsigned)mw >> (8 * b));
                cmax = max(cmax, v);
            }
            U[row * SCAN_P + j] = cmax;
        }
    }
    __syncthreads();
    // Pass B: running gmax per row (sequential, 128 cheap steps)
    if (tid < QROWS) {
        int g = -128;
        int* urow = U + tid * SCAN_P;
        for (int j = 0; j < 128; j++) {
            int c = urow[j];
            if (c > g) g = c;
            urow[j] = (int)((unsigned)(g + 128) << 16);
        }
        gmaxs[tid] = g;
    }
    __syncthreads();
    // Pass C: e_j per chunk given gmax_j (parallel)
    {
        int row = tid >> 3, seg = tid & 7;
        const int* srow = (const int*)&S[row * SW];
        int* urow = U + row * SCAN_P;
        #pragma unroll
        for (int cc = 0; cc < 16; cc++) {
            int j = cc * 8 + seg;
            unsigned pk = (unsigned)urow[j];
            int g = (int)(pk >> 16) - 128;
            int4 wv = *(const int4*)&srow[j * 4];
            int words[4] = {wv.x, wv.y, wv.z, wv.w};
            int es = 0;
            #pragma unroll
            for (int jw = 0; jw < 4; jw++) {
                int wvv = words[jw];
                #pragma unroll
                for (int b = 0; b < 4; b++) {
                    int xv = (int)(int8_t)((unsigned)wvv >> (8 * b));
                    int df = g - xv;              // >= 0
                    es += (df < 9) ? (256 >> df) : 0;
                }
            }
            urow[j] = (int)(pk | (unsigned)es);   // es <= 4096, fits 16 bits
        }
    }
    __syncthreads();
    // Pass D: exact sequential combine ps = (ps >> delta) + e
    if (tid < QROWS) {
        const int* urow = U + tid * SCAN_P;
        int ps = 0, gprev = -128;
        for (int j = 0; j < 128; j++) {
            unsigned pk = (unsigned)urow[j];
            int g = (int)(pk >> 16) - 128;
            int e = (int)(pk & 0xFFFFu);
            int sh = g - gprev;                   // >= 0
            ps = (sh < 31) ? (ps >> sh) : 0;
            ps += e;
            gprev = g;
        }
        invs[tid] = 65280 / ps;                   // exact == floor(65280.0/ps)
    }
    __syncthreads();

    // ---- prefetch V tile 0 while doing phase 2b ----
    #pragma unroll
    for (int it = 0; it < 16; it++) pre[it] = Vw[tid + it * 256];

    // -------- Phase 2b: logits -> attn bytes, in place (interleaved) --------
    {
        int q = tid >> 3, seg = tid & 7;
        int gm = gmaxs[q];
        unsigned inv = (unsigned)invs[q];
        for (int c = 0; c < 64; c++) {
            int w = c * 8 + seg;                  // conflict-free
            unsigned xw = S[q * SW + w];
            unsigned o = 0;
            #pragma unroll
            for (int b = 0; b < 4; b++) {
                int xv = (int)(int8_t)(xw >> (8 * b));
                int df = gm - xv;
                if (df > 31) df = 31;
                o |= (inv >> df) << (8 * b);
            }
            S[q * SW + w] = o;
        }
    }
    __syncthreads();
    #pragma unroll
    for (int it = 0; it < 16; it++) {
        int idx = tid + it * 256;
        U[(idx >> 6) * VPAD + (idx & 63)] = pre[it];   // vb[kwl][d]
    }
    __syncthreads();

    // -------- Phase 3: attn @ V, 8 tiles of 64 kwords, k-split x4 --------
    const int wq = warp >> 2;             // q half (0..1)
    const int wk = warp & 3;              // k quarter (0..3)
    const int lq = lane >> 3;             // q sub (4)
    const int ld = lane & 7;              // d group (8)
    const int qr0 = wq * 16 + lq * 4;     // thread's first q row

    int acc3[4][8];
    #pragma unroll
    for (int i = 0; i < 4; i++)
        #pragma unroll
        for (int j = 0; j < 8; j++) acc3[i][j] = 0;

    for (int t = 0; t < 8; t++) {
        int cur = t & 1;
        if (t + 1 < 8) {
            const int* Vt = Vw + (size_t)(t + 1) * 4096;
            #pragma unroll
            for (int it = 0; it < 16; it++) pre[it] = Vt[tid + it * 256];
        }
        const int* vbc = U + cur * 64 * VPAD;
        #pragma unroll
        for (int kki = 0; kki < 16; kki++) {
            int kwl = wk * 16 + kki;
            unsigned a[4];
            #pragma unroll
            for (int i = 0; i < 4; i++)
                a[i] = S[(qr0 + i) * SW + t * 64 + kwl];           // 4-distinct broadcast
            int4 b0 = *(const int4*)&vbc[kwl * VPAD + ld * 4];      // CF stride 4
            int4 b1 = *(const int4*)&vbc[kwl * VPAD + 32 + ld * 4];
            int b[8] = {b0.x, b0.y, b0.z, b0.w, b1.x, b1.y, b1.z, b1.w};
            #pragma unroll
            for (int i = 0; i < 4; i++)
                #pragma unroll
                for (int j = 0; j < 8; j++)
                    acc3[i][j] = dp4a_us(a[i], b[j], acc3[i][j]);
        }
        __syncthreads();
        if (t + 1 < 8) {
            int nb = (t + 1) & 1;
            #pragma unroll
            for (int it = 0; it < 16; it++) {
                int idx = tid + it * 256;
                U[nb * 64 * VPAD + (idx >> 6) * VPAD + (idx & 63)] = pre[it];
            }
            __syncthreads();
        }
    }

    // ---- reduction across the 4 k-groups via union region (red[4][32][64]) ----
    __syncthreads();                      // all vb reads done; reuse U
    #pragma unroll
    for (int i = 0; i < 4; i++) {
        *(int4*)&U[wk * 2048 + (qr0 + i) * 64 + ld * 4]      = make_int4(acc3[i][0], acc3[i][1], acc3[i][2], acc3[i][3]);
        *(int4*)&U[wk * 2048 + (qr0 + i) * 64 + 32 + ld * 4] = make_int4(acc3[i][4], acc3[i][5], acc3[i][6], acc3[i][7]);
    }
    __syncthreads();

    {
        const int b_ = bh / NHEADS, h = bh % NHEADS;
        int q = tid >> 3;                 // 0..31
        int d0 = (tid & 7) * 8;
        int4 s0 = make_int4(0,0,0,0), s1 = make_int4(0,0,0,0);
        #pragma unroll
        for (int g = 0; g < 4; g++) {
            int4 a0 = *(const int4*)&U[g * 2048 + q * 64 + d0];
            int4 a1 = *(const int4*)&U[g * 2048 + q * 64 + d0 + 4];
            s0.x += a0.x; s0.y += a0.y; s0.z += a0.z; s0.w += a0.w;
            s1.x += a1.x; s1.y += a1.y; s1.z += a1.z; s1.w += a1.w;
        }
        unsigned lo = pack_bytes(clamp_i8(s0.x >> 8), clamp_i8(s0.y >> 8),
                                 clamp_i8(s0.z >> 8), clamp_i8(s0.w >> 8));
        unsigned hi = pack_bytes(clamp_i8(s1.x >> 8), clamp_i8(s1.y >> 8),
                                 clamp_i8(s1.z >> 8), clamp_i8(s1.w >> 8));
        *(int2*)(g_ctx + ((size_t)(b_ * SEQ + q0 + q)) * DMODEL + h * HD + d0) = make_int2((int)lo, (int)hi);
    }
}

// ---------------------------------------------------------------------------
// Kernel 3: out = requantize(ctx @ wo^T + bo, 256, 7), f32x2 + split B cols
// Unchanged from R9 (verified rel_err 0).
// ---------------------------------------------------------------------------
__global__ void __launch_bounds__(256, 2) out_kernel(
    const float* __restrict__ wo, const float* __restrict__ bo,
    float* __restrict__ out)
{
    __shared__ float cs[16][132];
    __shared__ float ws[16][132];

    const int m0 = blockIdx.x * 128;
    const int n0 = blockIdx.y * 128;
    const int tid = threadIdx.x, tx = tid & 15, ty = tid >> 4;

    unsigned long long acc[4][8];
    #pragma unroll
    for (int i = 0; i < 4; i++)
        #pragma unroll
        for (int j = 0; j < 8; j++) acc[i][j] = 0ULL;

    for (int k0 = 0; k0 < DMODEL; k0 += 16) {
        #pragma unroll
        for (int it = 0; it < 8; it++) {
            int r = ty + it * 16;
            cs[tx][r] = (float)g_ctx[(size_t)(m0 + r) * DMODEL + k0 + tx];
            ws[tx][r] = wo[(size_t)(n0 + r) * DMODEL + k0 + tx];
        }
        __syncthreads();
        #pragma unroll
        for (int kk = 0; kk < 16; kk++) {
            ulonglong2 a01 = *(ulonglong2*)&cs[kk][ty * 8];
            ulonglong2 a23 = *(ulonglong2*)&cs[kk][ty * 8 + 4];
            float4 bA = *(float4*)&ws[kk][tx * 4];
            float4 bB = *(float4*)&ws[kk][64 + tx * 4];
            unsigned long long a[4] = {a01.x, a01.y, a23.x, a23.y};
            unsigned long long bd[8];
            bd[0] = pack2(bA.x, bA.x); bd[1] = pack2(bA.y, bA.y);
            bd[2] = pack2(bA.z, bA.z); bd[3] = pack2(bA.w, bA.w);
            bd[4] = pack2(bB.x, bB.x); bd[5] = pack2(bB.y, bB.y);
            bd[6] = pack2(bB.z, bB.z); bd[7] = pack2(bB.w, bB.w);
            #pragma unroll
            for (int i = 0; i < 4; i++)
                #pragma unroll
                for (int j = 0; j < 8; j++)
                    ffma2(acc[i][j], a[i], bd[j]);
        }
        __syncthreads();
    }

    float bb[8];
    #pragma unroll
    for (int e = 0; e < 4; e++) bb[e] = bo[n0 + tx * 4 + e];
    #pragma unroll
    for (int e = 4; e < 8; e++) bb[e] = bo[n0 + 64 + tx * 4 + (e - 4)];

    #pragma unroll
    for (int mp = 0; mp < 4; mp++) {
        #pragma unroll
        for (int par = 0; par < 2; par++) {
            int m = m0 + ty * 8 + mp * 2 + par;
            float vals[8];
            #pragma unroll
            for (int j = 0; j < 8; j++) {
                float lo, hi; unpack2(acc[mp][j], lo, hi);
                float v = (par == 0) ? lo : hi;
                float r = floorf(((v + bb[j]) * 256.0f) * (1.0f / 128.0f));
                vals[j] = fminf(fmaxf(r, -128.0f), 127.0f);
            }
            *(float4*)&out[(size_t)m * DMODEL + n0 + tx * 4] =
                make_float4(vals[0], vals[1], vals[2], vals[3]);
            *(float4*)&out[(size_t)m * DMODEL + n0 + 64 + tx * 4] =
                make_float4(vals[4], vals[5], vals[6], vals[7]);
        }
    }
}

// ---------------------------------------------------------------------------
extern "C" void kernel_launch(void* const* d_in, const int* in_sizes, int n_in,
                              void* d_out, int out_size)
{
    const float* x  = (const float*)d_in[0];
    const float* wq = (const float*)d_in[1];
    const float* bq = (const float*)d_in[2];
    const float* wk = (const float*)d_in[3];
    const float* bk = (const float*)d_in[4];
    const float* wv = (const float*)d_in[5];
    const float* bv = (const float*)d_in[6];
    const float* wo = (const float*)d_in[7];
    const float* bo = (const float*)d_in[8];
    float* out = (float*)d_out;

    cudaFuncSetAttribute(attn_fused, cudaFuncAttributeMaxDynamicSharedMemorySize,
                         ATTN_SMEM_BYTES);

    proj_kernel<<<dim3(64, 3, 3), 256>>>(x, wq, bq, wk, bk, wv, bv);
    attn_fused<<<dim3(64, 24), 256, ATTN_SMEM_BYTES>>>();
    out_kernel<<<dim3(64, 3), 256>>>(wo, bo, out);
}

// round 12
// speedup vs baseline: 1.9531x; 1.1620x over previous
#include <cuda_runtime.h>
#include <cstdint>
#include <cstddef>

#define BATCH 4
#define SEQ 2048
#define DMODEL 384
#define NHEADS 6
#define HD 64
#define BH (BATCH*NHEADS)      /* 24 */

// ---------------- scratch (static device arrays; no cudaMalloc allowed) -------
__device__ __align__(16) int8_t g_Q  [(size_t)BH*SEQ*HD];        // [bh][n][d]
__device__ __align__(16) int8_t g_K  [(size_t)BH*SEQ*HD];        // [bh][n][d]
// V packed words: word (bh, nblk, d) = V[nblk*4 .. +3][d] bytes (packed along n)
__device__ __align__(16) int8_t g_Vp [(size_t)BH*(SEQ/4)*HD*4];  // [bh][nblk 512][d 64] int32 words
__device__ __align__(16) int8_t g_ctx[(size_t)BATCH*SEQ*DMODEL]; // [b][n][h*hd]

__device__ __forceinline__ int dp4a_us(unsigned a, int b, int c) {
    int d;
    asm("dp4a.u32.s32 %0, %1, %2, %3;" : "=r"(d) : "r"(a), "r"(b), "r"(c));
    return d;
}
__device__ __forceinline__ void ffma2(unsigned long long& d,
                                      unsigned long long a, unsigned long long b) {
    asm("fma.rn.f32x2 %0, %1, %2, %0;" : "+l"(d) : "l"(a), "l"(b));
}
__device__ __forceinline__ unsigned long long pack2(float lo, float hi) {
    unsigned long long p;
    asm("mov.b64 %0, {%1, %2};" : "=l"(p) : "f"(lo), "f"(hi));
    return p;
}
__device__ __forceinline__ void unpack2(unsigned long long p, float& lo, float& hi) {
    asm("mov.b64 {%0, %1}, %2;" : "=f"(lo), "=f"(hi) : "l"(p));
}
__device__ __forceinline__ int clamp_i8(int v) {
    return v < -128 ? -128 : (v > 127 ? 127 : v);
}
__device__ __forceinline__ unsigned pack_bytes(int v0, int v1, int v2, int v3) {
    return  ((unsigned)(unsigned char)(int8_t)v0)
          | (((unsigned)(unsigned char)(int8_t)v1) << 8)
          | (((unsigned)(unsigned char)(int8_t)v2) << 16)
          | (((unsigned)(unsigned char)(int8_t)v3) << 24);
}

// ---------------------------------------------------------------------------
// Kernel 1: QKV projection (f32x2 FMA, M-dim pairing, stride-4 CF B loads).
// Unchanged from R9/R10 (verified rel_err 0).
// ---------------------------------------------------------------------------
__global__ void __launch_bounds__(256, 2) proj_kernel(
    const float* __restrict__ x,
    const float* __restrict__ wq, const float* __restrict__ bq,
    const float* __restrict__ wk, const float* __restrict__ bk,
    const float* __restrict__ wv, const float* __restrict__ bv)
{
    __shared__ float xs[16][132];      // [kk][m]
    __shared__ float ws[16][132];      // [kk][n]
    __shared__ int8_t vq[128][132];    // V transpose staging (z==2)

    const int z = blockIdx.z;
    const float* w    = (z == 0) ? wq : ((z == 1) ? wk : wv);
    const float* bias = (z == 0) ? bq : ((z == 1) ? bk : bv);
    const int m0 = blockIdx.x * 128;
    const int n0 = blockIdx.y * 128;
    const int tid = threadIdx.x, tx = tid & 15, ty = tid >> 4;

    unsigned long long acc[4][8];      // [m-pair][n]
    #pragma unroll
    for (int i = 0; i < 4; i++)
        #pragma unroll
        for (int j = 0; j < 8; j++) acc[i][j] = 0ULL;

    for (int k0 = 0; k0 < DMODEL; k0 += 16) {
        #pragma unroll
        for (int it = 0; it < 8; it++) {
            int r = ty + it * 16;
            xs[tx][r] = x[(size_t)(m0 + r) * DMODEL + k0 + tx];
            ws[tx][r] = w[(size_t)(n0 + r) * DMODEL + k0 + tx];
        }
        __syncthreads();
        #pragma unroll
        for (int kk = 0; kk < 16; kk++) {
            ulonglong2 a01 = *(ulonglong2*)&xs[kk][ty * 8];
            ulonglong2 a23 = *(ulonglong2*)&xs[kk][ty * 8 + 4];
            float4 bA = *(float4*)&ws[kk][tx * 4];        // cols tx*4..+3
            float4 bB = *(float4*)&ws[kk][64 + tx * 4];   // cols 64+tx*4..+3
            unsigned long long a[4] = {a01.x, a01.y, a23.x, a23.y};
            unsigned long long bd[8];
            bd[0] = pack2(bA.x, bA.x); bd[1] = pack2(bA.y, bA.y);
            bd[2] = pack2(bA.z, bA.z); bd[3] = pack2(bA.w, bA.w);
            bd[4] = pack2(bB.x, bB.x); bd[5] = pack2(bB.y, bB.y);
            bd[6] = pack2(bB.z, bB.z); bd[7] = pack2(bB.w, bB.w);
            #pragma unroll
            for (int i = 0; i < 4; i++)
                #pragma unroll
                for (int j = 0; j < 8; j++)
                    ffma2(acc[i][j], a[i], bd[j]);
        }
        __syncthreads();
    }

    float bb[8];
    #pragma unroll
    for (int e = 0; e < 4; e++) bb[e] = bias[n0 + tx * 4 + e];
    #pragma unroll
    for (int e = 4; e < 8; e++) bb[e] = bias[n0 + 64 + tx * 4 + (e - 4)];

    if (z < 2) {
        int8_t* dst = (z == 0) ? g_Q : g_K;
        const int hA = n0 >> 6, hB = hA + 1;   // n0 multiple of 128
        #pragma unroll
        for (int mp = 0; mp < 4; mp++) {
            #pragma unroll
            for (int par = 0; par < 2; par++) {
                int m = m0 + ty * 8 + mp * 2 + par;
                int b_ = m >> 11, n = m & 2047;
                unsigned wA = 0, wB = 0;
                #pragma unroll
                for (int j = 0; j < 8; j++) {
                    float lo, hi; unpack2(acc[mp][j], lo, hi);
                    float v = (par == 0) ? lo : hi;
                    float r = floorf(((v + bb[j]) * 16384.0f) * (1.0f / 256.0f));
                    r = fminf(fmaxf(r, -128.0f), 127.0f);
                    unsigned u = (unsigned)(unsigned char)(int8_t)(int)r;
                    if (j < 4) wA |= u << (8 * j);
                    else       wB |= u << (8 * (j - 4));
                }
                ((int*)dst)[((size_t)(b_ * NHEADS + hA) * SEQ + n) * 16 + tx] = (int)wA;
                ((int*)dst)[((size_t)(b_ * NHEADS + hB) * SEQ + n) * 16 + tx] = (int)wB;
            }
        }
    } else {
        #pragma unroll
        for (int mp = 0; mp < 4; mp++) {
            #pragma unroll
            for (int j = 0; j < 8; j++) {
                float lo, hi; unpack2(acc[mp][j], lo, hi);
                float r0 = floorf(((lo + bb[j]) * 16384.0f) * (1.0f / 256.0f));
                r0 = fminf(fmaxf(r0, -128.0f), 127.0f);
                float r1 = floorf(((hi + bb[j]) * 16384.0f) * (1.0f / 256.0f));
                r1 = fminf(fmaxf(r1, -128.0f), 127.0f);
                int col = (j < 4) ? (tx * 4 + j) : (64 + tx * 4 + (j - 4));
                vq[col][ty * 8 + mp * 2]     = (int8_t)(int)r0;
                vq[col][ty * 8 + mp * 2 + 1] = (int8_t)(int)r1;
            }
        }
        __syncthreads();
        int b_ = m0 >> 11;
        int nloc = m0 & 2047;
        #pragma unroll
        for (int it = 0; it < 16; it++) {
            int idx = tid + it * 256;              // 0..4095
            int col = idx & 127;
            int j4  = idx >> 7;
            int word = *(int*)&vq[col][j4 * 4];
            int cg = n0 + col, h = cg >> 6, d = cg & 63;
            size_t nblk = (size_t)((nloc >> 2) + j4);
            ((int*)g_Vp)[((size_t)(b_ * NHEADS + h) * (SEQ/4) + nblk) * HD + d] = word;
        }
    }
}

// ---------------------------------------------------------------------------
// Kernel 2: fused attention, 256 threads, 32-q strips, 2 CTAs/SM.
// Phase 1: logits, 32q x 256key tiles (dp4a, CF loads) - unchanged from R10
// Phase 2: ITA scan, exact 8x-parallel decomposition + relevant-chunk lists
// Phase 3: EXACT SPARSE attn@V - only chunks with es>0 (others are exact 0s);
//          attn words computed on the fly, V read directly from L2, no staging.
// ---------------------------------------------------------------------------
#define QROWS 32
#define SW 516                                    /* padded S row (words) */
#define QSP 36                                    /* qs row pad */
#define KP 260                                    /* K tile row pad (words) */
#define U_INTS 8704                               /* union: kb / scan */
#define SCAN_P 130                                /* scan scratch row pad */
#define ATTN_SMEM_INTS (QROWS*SW + 16*QSP + U_INTS + 1440)
#define ATTN_SMEM_BYTES (ATTN_SMEM_INTS * 4)      /* ~106.4 KB -> 2 CTAs/SM */

extern __shared__ int smem_raw[];

__global__ void __launch_bounds__(256, 2) attn_fused()
{
    int* SM = smem_raw;
    unsigned* S = (unsigned*)SM;                  // [32][SW] logits words
    int* qs    = SM + QROWS * SW;                 // [16][QSP] transposed Q
    int* U     = qs + 16 * QSP;                   // union region (8704 ints)
    int* gmaxs = U + U_INTS;                      // [32]
    int* invs  = gmaxs + QROWS;                   // [32]
    int* cnt   = invs + QROWS;                    // [32] relevant-chunk counts
    unsigned char* lst = (unsigned char*)(cnt + QROWS);   // [32][128] chunk ids

    const int bh = blockIdx.y;
    const int q0 = blockIdx.x * QROWS;
    const int tid = threadIdx.x;
    const int lane = tid & 31, warp = tid >> 5;   // 8 warps

    const int* Qw = (const int*)g_Q + (size_t)bh * SEQ * (HD/4) + (size_t)q0 * (HD/4);
    const int* Kw = (const int*)g_K + (size_t)bh * SEQ * (HD/4);

    // ---- Q transposed: qs[kk][qrow] (512 words) ----
    #pragma unroll
    for (int it = 0; it < 2; it++) {
        int idx = tid + it * 256;
        qs[(idx & 15) * QSP + (idx >> 4)] = Qw[idx];
    }
    // ---- prefetch K tile 0 (256 rows x 16 words = 4096 ints) ----
    int pre[16];
    #pragma unroll
    for (int it = 0; it < 16; it++) pre[it] = Kw[tid + it * 256];
    #pragma unroll
    for (int it = 0; it < 16; it++) {
        int idx = tid + it * 256;
        U[(idx & 15) * KP + (idx >> 4)] = pre[it];
    }
    __syncthreads();

    // -------- Phase 1: logits, 8 tiles of 256 keys (unchanged) --------
    for (int t = 0; t < 8; t++) {
        int cur = t & 1;
        if (t + 1 < 8) {
            const int* Kt = Kw + (size_t)(t + 1) * 4096;
            #pragma unroll
            for (int it = 0; it < 16; it++) pre[it] = Kt[tid + it * 256];
        }
        const int* kbc = U + cur * 16 * KP;
        int acc[4][8];
        #pragma unroll
        for (int i = 0; i < 4; i++)
            #pragma unroll
            for (int j = 0; j < 8; j++) acc[i][j] = 0;
        #pragma unroll
        for (int kk = 0; kk < 16; kk++) {
            int4 av = *(const int4*)&qs[kk * QSP + warp * 4];        // broadcast
            int4 b0 = *(const int4*)&kbc[kk * KP + lane * 4];        // CF stride 4
            int4 b1 = *(const int4*)&kbc[kk * KP + 128 + lane * 4];
            int a[4] = {av.x, av.y, av.z, av.w};
            int b[8] = {b0.x, b0.y, b0.z, b0.w, b1.x, b1.y, b1.z, b1.w};
            #pragma unroll
            for (int i = 0; i < 4; i++)
                #pragma unroll
                for (int j = 0; j < 8; j++)
                    acc[i][j] = __dp4a(a[i], b[j], acc[i][j]);
        }
        #pragma unroll
        for (int i = 0; i < 4; i++) {
            unsigned w0 = pack_bytes(clamp_i8((acc[i][0]*5) >> 12), clamp_i8((acc[i][1]*5) >> 12),
                                     clamp_i8((acc[i][2]*5) >> 12), clamp_i8((acc[i][3]*5) >> 12));
            unsigned w1 = pack_bytes(clamp_i8((acc[i][4]*5) >> 12), clamp_i8((acc[i][5]*5) >> 12),
                                     clamp_i8((acc[i][6]*5) >> 12), clamp_i8((acc[i][7]*5) >> 12));
            S[(warp * 4 + i) * SW + t * 64 + lane]      = w0;
            S[(warp * 4 + i) * SW + t * 64 + 32 + lane] = w1;
        }
        __syncthreads();
        if (t + 1 < 8) {
            int nb = (t + 1) & 1;
            #pragma unroll
            for (int it = 0; it < 16; it++) {
                int idx = tid + it * 256;
                U[nb * 16 * KP + (idx & 15) * KP + (idx >> 4)] = pre[it];
            }
            __syncthreads();
        }
    }

    // -------- Phase 2: ITA scan, exact 8x-parallel decomposition --------
    // Pass A: per-chunk maxima (chunk = 16 keys). 8 threads per row, interleaved.
    {
        int row = tid >> 3, seg = tid & 7;        // row 0..31
        const int* srow = (const int*)&S[row * SW];
        #pragma unroll
        for (int cc = 0; cc < 16; cc++) {
            int j = cc * 8 + seg;                 // conflict-free
            int4 wv = *(const int4*)&srow[j * 4];
            int mw = __vmaxs4(__vmaxs4(wv.x, wv.y), __vmaxs4(wv.z, wv.w));
            int cmax = -128;
            #pragma unroll
            for (int b = 0; b < 4; b++) {
                int v = (int)(int8_t)((unsigned)mw >> (8 * b));
                cmax = max(cmax, v);
            }
            U[row * SCAN_P + j] = cmax;
        }
    }
    __syncthreads();
    // Pass B: running gmax per row (sequential, 128 cheap steps); zero cnt.
    if (tid < QROWS) {
        int g = -128;
        int* urow = U + tid * SCAN_P;
        for (int j = 0; j < 128; j++) {
            int c = urow[j];
            if (c > g) g = c;
            urow[j] = (int)((unsigned)(g + 128) << 16);
        }
        gmaxs[tid] = g;
        cnt[tid] = 0;
    }
    __syncthreads();
    // Pass C: e_j per chunk given gmax_j (parallel); build relevant-chunk lists.
    // es == 0  <=>  all 16 keys have df >= 9  =>  all attn bytes exactly 0.
    {
        int row = tid >> 3, seg = tid & 7;
        const int* srow = (const int*)&S[row * SW];
        int* urow = U + row * SCAN_P;
        #pragma unroll
        for (int cc = 0; cc < 16; cc++) {
            int j = cc * 8 + seg;
            unsigned pk = (unsigned)urow[j];
            int g = (int)(pk >> 16) - 128;
            int4 wv = *(const int4*)&srow[j * 4];
            int words[4] = {wv.x, wv.y, wv.z, wv.w};
            int es = 0;
            #pragma unroll
            for (int jw = 0; jw < 4; jw++) {
                int wvv = words[jw];
                #pragma unroll
                for (int b = 0; b < 4; b++) {
                    int xv = (int)(int8_t)((unsigned)wvv >> (8 * b));
                    int df = g - xv;              // >= 0
                    es += (df < 9) ? (256 >> df) : 0;
                }
            }
            urow[j] = (int)(pk | (unsigned)es);   // es <= 4096, fits 16 bits
            if (es) {
                int pos = atomicAdd(&cnt[row], 1);
                lst[row * 128 + pos] = (unsigned char)j;
            }
        }
    }
    __syncthreads();
    // Pass D: exact sequential combine ps = (ps >> delta) + e
    if (tid < QROWS) {
        const int* urow = U + tid * SCAN_P;
        int ps = 0, gprev = -128;
        for (int j = 0; j < 128; j++) {
            unsigned pk = (unsigned)urow[j];
            int g = (int)(pk >> 16) - 128;
            int e = (int)(pk & 0xFFFFu);
            int sh = g - gprev;                   // >= 0
            ps = (sh < 31) ? (ps >> sh) : 0;
            ps += e;
            gprev = g;
        }
        invs[tid] = 65280 / ps;                   // exact == floor(65280.0/ps)
    }
    __syncthreads();

    // -------- Phase 3: EXACT SPARSE attn @ V --------
    // Warp handles 4 rows; lanes cover d (lane, lane+32). Only relevant chunks;
    // skipped chunks have all-zero attn words (exact). V read straight from L2.
    {
        const int* Vg = (const int*)g_Vp + (size_t)bh * (SEQ/4) * HD;
        const int b_ = bh / NHEADS, h = bh % NHEADS;
        #pragma unroll
        for (int r = 0; r < 4; r++) {
            int row = warp * 4 + r;
            int n = cnt[row];
            int gm = gmaxs[row];
            unsigned inv = (unsigned)invs[row];
            int acc0 = 0, acc1 = 0;
            for (int ii = 0; ii < n; ii++) {
                int j = (int)lst[row * 128 + ii];                 // chunk id 0..127
                int4 lw = *(const int4*)&S[row * SW + j * 4];     // 4 logits words (broadcast)
                int lwa[4] = {lw.x, lw.y, lw.z, lw.w};
                #pragma unroll
                for (int kw = 0; kw < 4; kw++) {
                    unsigned xw = (unsigned)lwa[kw];
                    unsigned aw = 0;
                    #pragma unroll
                    for (int bb2 = 0; bb2 < 4; bb2++) {
                        int xv = (int)(int8_t)(xw >> (8 * bb2));
                        int df = gm - xv;
                        if (df > 31) df = 31;
                        aw |= (inv >> df) << (8 * bb2);
                    }
                    int base = (j * 4 + kw) * 64;                  // kword * HD
                    acc0 = dp4a_us(aw, Vg[base + lane],      acc0);
                    acc1 = dp4a_us(aw, Vg[base + 32 + lane], acc1);
                }
            }
            int q = q0 + row;
            int8_t* dst = g_ctx + ((size_t)(b_ * SEQ + q)) * DMODEL + h * HD;
            dst[lane]      = (int8_t)clamp_i8(acc0 >> 8);         // floor(acc/256)
            dst[32 + lane] = (int8_t)clamp_i8(acc1 >> 8);
        }
    }
}

// ---------------------------------------------------------------------------
// Kernel 3: out = requantize(ctx @ wo^T + bo, 256, 7), f32x2 + split B cols
// Unchanged from R9/R10 (verified rel_err 0).
// ---------------------------------------------------------------------------
__global__ void __launch_bounds__(256, 2) out_kernel(
    const float* __restrict__ wo, const float* __restrict__ bo,
    float* __restrict__ out)
{
    __shared__ float cs[16][132];
    __shared__ float ws[16][132];

    const int m0 = blockIdx.x * 128;
    const int n0 = blockIdx.y * 128;
    const int tid = threadIdx.x, tx = tid & 15, ty = tid >> 4;

    unsigned long long acc[4][8];
    #pragma unroll
    for (int i = 0; i < 4; i++)
        #pragma unroll
        for (int j = 0; j < 8; j++) acc[i][j] = 0ULL;

    for (int k0 = 0; k0 < DMODEL; k0 += 16) {
        #pragma unroll
        for (int it = 0; it < 8; it++) {
            int r = ty + it * 16;
            cs[tx][r] = (float)g_ctx[(size_t)(m0 + r) * DMODEL + k0 + tx];
            ws[tx][r] = wo[(size_t)(n0 + r) * DMODEL + k0 + tx];
        }
        __syncthreads();
        #pragma unroll
        for (int kk = 0; kk < 16; kk++) {
            ulonglong2 a01 = *(ulonglong2*)&cs[kk][ty * 8];
            ulonglong2 a23 = *(ulonglong2*)&cs[kk][ty * 8 + 4];
            float4 bA = *(float4*)&ws[kk][tx * 4];
            float4 bB = *(float4*)&ws[kk][64 + tx * 4];
            unsigned long long a[4] = {a01.x, a01.y, a23.x, a23.y};
            unsigned long long bd[8];
            bd[0] = pack2(bA.x, bA.x); bd[1] = pack2(bA.y, bA.y);
            bd[2] = pack2(bA.z, bA.z); bd[3] = pack2(bA.w, bA.w);
            bd[4] = pack2(bB.x, bB.x); bd[5] = pack2(bB.y, bB.y);
            bd[6] = pack2(bB.z, bB.z); bd[7] = pack2(bB.w, bB.w);
            #pragma unroll
            for (int i = 0; i < 4; i++)
                #pragma unroll
                for (int j = 0; j < 8; j++)
                    ffma2(acc[i][j], a[i], bd[j]);
        }
        __syncthreads();
    }

    float bb[8];
    #pragma unroll
    for (int e = 0; e < 4; e++) bb[e] = bo[n0 + tx * 4 + e];
    #pragma unroll
    for (int e = 4; e < 8; e++) bb[e] = bo[n0 + 64 + tx * 4 + (e - 4)];

    #pragma unroll
    for (int mp = 0; mp < 4; mp++) {
        #pragma unroll
        for (int par = 0; par < 2; par++) {
            int m = m0 + ty * 8 + mp * 2 + par;
            float vals[8];
            #pragma unroll
            for (int j = 0; j < 8; j++) {
                float lo, hi; unpack2(acc[mp][j], lo, hi);
                float v = (par == 0) ? lo : hi;
                float r = floorf(((v + bb[j]) * 256.0f) * (1.0f / 128.0f));
                vals[j] = fminf(fmaxf(r, -128.0f), 127.0f);
            }
            *(float4*)&out[(size_t)m * DMODEL + n0 + tx * 4] =
                make_float4(vals[0], vals[1], vals[2], vals[3]);
            *(float4*)&out[(size_t)m * DMODEL + n0 + 64 + tx * 4] =
                make_float4(vals[4], vals[5], vals[6], vals[7]);
        }
    }
}

// ---------------------------------------------------------------------------
extern "C" void kernel_launch(void* const* d_in, const int* in_sizes, int n_in,
                              void* d_out, int out_size)
{
    const float* x  = (const float*)d_in[0];
    const float* wq = (const float*)d_in[1];
    const float* bq = (const float*)d_in[2];
    const float* wk = (const float*)d_in[3];
    const float* bk = (const float*)d_in[4];
    const float* wv = (const float*)d_in[5];
    const float* bv = (const float*)d_in[6];
    const float* wo = (const float*)d_in[7];
    const float* bo = (const float*)d_in[8];
    float* out = (float*)d_out;

    cudaFuncSetAttribute(attn_fused, cudaFuncAttributeMaxDynamicSharedMemorySize,
                         ATTN_SMEM_BYTES);

    proj_kernel<<<dim3(64, 3, 3), 256>>>(x, wq, bq, wk, bk, wv, bv);
    attn_fused<<<dim3(64, 24), 256, ATTN_SMEM_BYTES>>>();
    out_kernel<<<dim3(64, 3), 256>>>(wo, bo, out);
}

// round 13
// speedup vs baseline: 2.0667x; 1.0582x over previous
#include <cuda_runtime.h>
#include <cstdint>
#include <cstddef>

#define BATCH 4
#define SEQ 2048
#define DMODEL 384
#define NHEADS 6
#define HD 64
#define BH (BATCH*NHEADS)      /* 24 */

// ---------------- scratch (static device arrays; no cudaMalloc allowed) -------
__device__ __align__(16) int8_t g_Q  [(size_t)BH*SEQ*HD];        // [bh][n][d]
__device__ __align__(16) int8_t g_K  [(size_t)BH*SEQ*HD];        // [bh][n][d]
// V packed words: word (bh, nblk, d) = V[nblk*4 .. +3][d] bytes (packed along n)
__device__ __align__(16) int8_t g_Vp [(size_t)BH*(SEQ/4)*HD*4];  // [bh][nblk 512][d 64]
__device__ __align__(16) int8_t g_ctx[(size_t)BATCH*SEQ*DMODEL]; // [b][n][h*hd]

__device__ __forceinline__ int dp4a_us(unsigned a, int b, int c) {
    int d;
    asm("dp4a.u32.s32 %0, %1, %2, %3;" : "=r"(d) : "r"(a), "r"(b), "r"(c));
    return d;
}
__device__ __forceinline__ void ffma2(unsigned long long& d,
                                      unsigned long long a, unsigned long long b) {
    asm("fma.rn.f32x2 %0, %1, %2, %0;" : "+l"(d) : "l"(a), "l"(b));
}
__device__ __forceinline__ unsigned long long pack2(float lo, float hi) {
    unsigned long long p;
    asm("mov.b64 %0, {%1, %2};" : "=l"(p) : "f"(lo), "f"(hi));
    return p;
}
__device__ __forceinline__ void unpack2(unsigned long long p, float& lo, float& hi) {
    asm("mov.b64 {%0, %1}, %2;" : "=f"(lo), "=f"(hi) : "l"(p));
}
__device__ __forceinline__ int clamp_i8(int v) {
    return v < -128 ? -128 : (v > 127 ? 127 : v);
}
__device__ __forceinline__ unsigned pack_bytes(int v0, int v1, int v2, int v3) {
    return  ((unsigned)(unsigned char)(int8_t)v0)
          | (((unsigned)(unsigned char)(int8_t)v1) << 8)
          | (((unsigned)(unsigned char)(int8_t)v2) << 16)
          | (((unsigned)(unsigned char)(int8_t)v3) << 24);
}

// ---------------------------------------------------------------------------
// Kernel 1: QKV projection (f32x2 FMA) with double-buffered smem, vectorized
// LDG.128 prefetch, single sync per k-chunk. Math identical to R9-R11.
// ---------------------------------------------------------------------------
__global__ void __launch_bounds__(256, 2) proj_kernel(
    const float* __restrict__ x,
    const float* __restrict__ wq, const float* __restrict__ bq,
    const float* __restrict__ wk, const float* __restrict__ bk,
    const float* __restrict__ wv, const float* __restrict__ bv)
{
    __shared__ float xs[2][16][132];   // [buf][kk][m]
    __shared__ float ws[2][16][132];   // [buf][kk][n]
    __shared__ int8_t vq[128][132];    // V transpose staging (z==2)

    const int z = blockIdx.z;
    const float* w    = (z == 0) ? wq : ((z == 1) ? wk : wv);
    const float* bias = (z == 0) ? bq : ((z == 1) ? bk : bv);
    const int m0 = blockIdx.x * 128;
    const int n0 = blockIdx.y * 128;
    const int tid = threadIdx.x, tx = tid & 15, ty = tid >> 4;

    // staging geometry: idx = tid + it*256 (it<2): row = idx>>2, c4 = idx&3
    const int r0s = tid >> 2;          // row for it=0
    const int c4s = tid & 3;

    unsigned long long acc[4][8];
    #pragma unroll
    for (int i = 0; i < 4; i++)
        #pragma unroll
        for (int j = 0; j < 8; j++) acc[i][j] = 0ULL;

    float4 px[2], pw[2];
    // stage chunk 0
    #pragma unroll
    for (int it = 0; it < 2; it++) {
        int row = r0s + it * 64;
        px[it] = *(const float4*)&x[(size_t)(m0 + row) * DMODEL + c4s * 4];
        pw[it] = *(const float4*)&w[(size_t)(n0 + row) * DMODEL + c4s * 4];
    }
    #pragma unroll
    for (int it = 0; it < 2; it++) {
        int row = r0s + it * 64;
        xs[0][c4s*4+0][row] = px[it].x; xs[0][c4s*4+1][row] = px[it].y;
        xs[0][c4s*4+2][row] = px[it].z; xs[0][c4s*4+3][row] = px[it].w;
        ws[0][c4s*4+0][row] = pw[it].x; ws[0][c4s*4+1][row] = pw[it].y;
        ws[0][c4s*4+2][row] = pw[it].z; ws[0][c4s*4+3][row] = pw[it].w;
    }
    __syncthreads();

    for (int kc = 0; kc < 24; kc++) {
        const int cur = kc & 1;
        if (kc + 1 < 24) {
            int k0 = (kc + 1) * 16;
            #pragma unroll
            for (int it = 0; it < 2; it++) {
                int row = r0s + it * 64;
                px[it] = *(const float4*)&x[(size_t)(m0 + row) * DMODEL + k0 + c4s * 4];
                pw[it] = *(const float4*)&w[(size_t)(n0 + row) * DMODEL + k0 + c4s * 4];
            }
        }
        #pragma unroll
        for (int kk = 0; kk < 16; kk++) {
            ulonglong2 a01 = *(ulonglong2*)&xs[cur][kk][ty * 8];
            ulonglong2 a23 = *(ulonglong2*)&xs[cur][kk][ty * 8 + 4];
            float4 bA = *(float4*)&ws[cur][kk][tx * 4];
            float4 bB = *(float4*)&ws[cur][kk][64 + tx * 4];
            unsigned long long a[4] = {a01.x, a01.y, a23.x, a23.y};
            unsigned long long bd[8];
            bd[0] = pack2(bA.x, bA.x); bd[1] = pack2(bA.y, bA.y);
            bd[2] = pack2(bA.z, bA.z); bd[3] = pack2(bA.w, bA.w);
            bd[4] = pack2(bB.x, bB.x); bd[5] = pack2(bB.y, bB.y);
            bd[6] = pack2(bB.z, bB.z); bd[7] = pack2(bB.w, bB.w);
            #pragma unroll
            for (int i = 0; i < 4; i++)
                #pragma unroll
                for (int j = 0; j < 8; j++)
                    ffma2(acc[i][j], a[i], bd[j]);
        }
        if (kc + 1 < 24) {
            const int nb = (kc + 1) & 1;
            #pragma unroll
            for (int it = 0; it < 2; it++) {
                int row = r0s + it * 64;
                xs[nb][c4s*4+0][row] = px[it].x; xs[nb][c4s*4+1][row] = px[it].y;
                xs[nb][c4s*4+2][row] = px[it].z; xs[nb][c4s*4+3][row] = px[it].w;
                ws[nb][c4s*4+0][row] = pw[it].x; ws[nb][c4s*4+1][row] = pw[it].y;
                ws[nb][c4s*4+2][row] = pw[it].z; ws[nb][c4s*4+3][row] = pw[it].w;
            }
        }
        __syncthreads();
    }

    float bb[8];
    #pragma unroll
    for (int e = 0; e < 4; e++) bb[e] = bias[n0 + tx * 4 + e];
    #pragma unroll
    for (int e = 4; e < 8; e++) bb[e] = bias[n0 + 64 + tx * 4 + (e - 4)];

    if (z < 2) {
        int8_t* dst = (z == 0) ? g_Q : g_K;
        const int hA = n0 >> 6, hB = hA + 1;
        #pragma unroll
        for (int mp = 0; mp < 4; mp++) {
            #pragma unroll
            for (int par = 0; par < 2; par++) {
                int m = m0 + ty * 8 + mp * 2 + par;
                int b_ = m >> 11, n = m & 2047;
                unsigned wA = 0, wB = 0;
                #pragma unroll
                for (int j = 0; j < 8; j++) {
                    float lo, hi; unpack2(acc[mp][j], lo, hi);
                    float v = (par == 0) ? lo : hi;
                    float r = floorf(((v + bb[j]) * 16384.0f) * (1.0f / 256.0f));
                    r = fminf(fmaxf(r, -128.0f), 127.0f);
                    unsigned u = (unsigned)(unsigned char)(int8_t)(int)r;
                    if (j < 4) wA |= u << (8 * j);
                    else       wB |= u << (8 * (j - 4));
                }
                ((int*)dst)[((size_t)(b_ * NHEADS + hA) * SEQ + n) * 16 + tx] = (int)wA;
                ((int*)dst)[((size_t)(b_ * NHEADS + hB) * SEQ + n) * 16 + tx] = (int)wB;
            }
        }
    } else {
        #pragma unroll
        for (int mp = 0; mp < 4; mp++) {
            #pragma unroll
            for (int j = 0; j < 8; j++) {
                float lo, hi; unpack2(acc[mp][j], lo, hi);
                float r0 = floorf(((lo + bb[j]) * 16384.0f) * (1.0f / 256.0f));
                r0 = fminf(fmaxf(r0, -128.0f), 127.0f);
                float r1 = floorf(((hi + bb[j]) * 16384.0f) * (1.0f / 256.0f));
                r1 = fminf(fmaxf(r1, -128.0f), 127.0f);
                int col = (j < 4) ? (tx * 4 + j) : (64 + tx * 4 + (j - 4));
                vq[col][ty * 8 + mp * 2]     = (int8_t)(int)r0;
                vq[col][ty * 8 + mp * 2 + 1] = (int8_t)(int)r1;
            }
        }
        __syncthreads();
        int b_ = m0 >> 11;
        int nloc = m0 & 2047;
        #pragma unroll
        for (int it = 0; it < 16; it++) {
            int idx = tid + it * 256;
            int col = idx & 127;
            int j4  = idx >> 7;
            int word = *(int*)&vq[col][j4 * 4];
            int cg = n0 + col, h = cg >> 6, d = cg & 63;
            size_t nblk = (size_t)((nloc >> 2) + j4);
            ((int*)g_Vp)[((size_t)(b_ * NHEADS + h) * (SEQ/4) + nblk) * HD + d] = word;
        }
    }
}

// ---------------------------------------------------------------------------
// Kernel 2: fused attention, 256 threads, 16-q strips -> 3 CTAs/SM.
// Phase 1: logits, 16q x 256key tiles, thread 4q x 4keys, 1 sync/tile
// Phase 2: ITA scan (exact decomposition) with chunk-max early-out in Pass C
// Phase 3: exact sparse attn@V (only es>0 chunks; V straight from L2)
// ---------------------------------------------------------------------------
#define QROWS 16
#define SW 516                                    /* padded S row (words) */
#define QSP 20                                    /* qs row pad */
#define KP 260                                    /* K tile row pad (256 keys) */
#define UB_INTS (16*KP)                           /* one K buffer: 4160 ints */
#define U_INTS (2*UB_INTS)                        /* 8320 ints (scan fits: 16*130) */
#define SCAN_P 130
#define ATTN_SMEM_INTS (QROWS*SW + 16*QSP + U_INTS + 48 + 512 + 32)
#define ATTN_SMEM_BYTES (ATTN_SMEM_INTS * 4)      /* ~70 KB -> 3 CTAs/SM */

extern __shared__ int smem_raw[];

__global__ void __launch_bounds__(256, 3) attn_fused()
{
    int* SM = smem_raw;
    unsigned* S = (unsigned*)SM;                  // [16][SW] logits words
    int* qs    = SM + QROWS * SW;                 // [16][QSP] transposed Q
    int* U     = qs + 16 * QSP;                   // K double-buffer / scan scratch
    int* gmaxs = U + U_INTS;                      // [16]
    int* invs  = gmaxs + QROWS;                   // [16]
    int* cnt   = invs + QROWS;                    // [16]
    unsigned char* lst = (unsigned char*)(cnt + QROWS);   // [16][128]

    const int bh = blockIdx.y;
    const int q0 = blockIdx.x * QROWS;
    const int tid = threadIdx.x;
    const int lane = tid & 31, warp = tid >> 5;   // 8 warps
    const int rg = warp & 3;                      // row group (rows rg*4..+3)
    const int kh = warp >> 2;                     // key half (0/1)

    const int* Qw = (const int*)g_Q + (size_t)bh * SEQ * (HD/4) + (size_t)q0 * (HD/4);
    const int* Kw = (const int*)g_K + (size_t)bh * SEQ * (HD/4);

    // ---- Q transposed: qs[kk][qrow] (256 words) ----
    qs[(tid & 15) * QSP + (tid >> 4)] = Qw[(tid >> 4) * 16 + (tid & 15)];

    // ---- stage K tile 0 (256 keys x 16 words = 4096 ints) ----
    int pre[16];
    #pragma unroll
    for (int it = 0; it < 16; it++) pre[it] = Kw[tid + it * 256];
    #pragma unroll
    for (int it = 0; it < 16; it++) {
        int idx = tid + it * 256;
        U[(idx & 15) * KP + (idx >> 4)] = pre[it];
    }
    __syncthreads();

    // -------- Phase 1: logits, 8 tiles of 256 keys, single sync/tile --------
    for (int t = 0; t < 8; t++) {
        const int cur = t & 1;
        if (t + 1 < 8) {
            const int* Kt = Kw + (size_t)(t + 1) * 4096;
            #pragma unroll
            for (int it = 0; it < 16; it++) pre[it] = Kt[tid + it * 256];
        }
        const int* kbc = U + cur * UB_INTS;
        int acc[4][4];
        #pragma unroll
        for (int i = 0; i < 4; i++)
            #pragma unroll
            for (int j = 0; j < 4; j++) acc[i][j] = 0;
        #pragma unroll
        for (int kk = 0; kk < 16; kk++) {
            int4 av = *(const int4*)&qs[kk * QSP + rg * 4];              // broadcast
            int4 bv = *(const int4*)&kbc[kk * KP + kh * 128 + lane * 4]; // CF stride 4
            int a[4] = {av.x, av.y, av.z, av.w};
            int b[4] = {bv.x, bv.y, bv.z, bv.w};
            #pragma unroll
            for (int i = 0; i < 4; i++)
                #pragma unroll
                for (int j = 0; j < 4; j++)
                    acc[i][j] = __dp4a(a[i], b[j], acc[i][j]);
        }
        #pragma unroll
        for (int i = 0; i < 4; i++) {
            unsigned w0 = pack_bytes(clamp_i8((acc[i][0]*5) >> 12), clamp_i8((acc[i][1]*5) >> 12),
                                     clamp_i8((acc[i][2]*5) >> 12), clamp_i8((acc[i][3]*5) >> 12));
            S[(rg * 4 + i) * SW + t * 64 + kh * 32 + lane] = w0;
        }
        if (t + 1 < 8) {
            const int nb = (t + 1) & 1;
            #pragma unroll
            for (int it = 0; it < 16; it++) {
                int idx = tid + it * 256;
                U[nb * UB_INTS + (idx & 15) * KP + (idx >> 4)] = pre[it];
            }
        }
        __syncthreads();
    }

    // -------- Phase 2: ITA scan, exact decomposition --------
    // Pass A: per-chunk maxima. 16 threads per row, interleaved chunks.
    {
        int row = tid >> 4, seg = tid & 15;
        const int* srow = (const int*)&S[row * SW];
        #pragma unroll
        for (int cc = 0; cc < 8; cc++) {
            int j = cc * 16 + seg;                // conflict-free
            int4 wv = *(const int4*)&srow[j * 4];
            int mw = __vmaxs4(__vmaxs4(wv.x, wv.y), __vmaxs4(wv.z, wv.w));
            int cmax = -128;
            #pragma unroll
            for (int b = 0; b < 4; b++) {
                int v = (int)(int8_t)((unsigned)mw >> (8 * b));
                cmax = max(cmax, v);
            }
            U[row * SCAN_P + j] = cmax;
        }
    }
    __syncthreads();
    // Pass B: running gmax per row; pack (gmax+128)<<24 | (cmax+128)<<16.
    if (tid < QROWS) {
        int g = -128;
        int* urow = U + tid * SCAN_P;
        for (int j = 0; j < 128; j++) {
            int c = urow[j];
            if (c > g) g = c;
            urow[j] = (int)(((unsigned)(g + 128) << 24) | ((unsigned)(c + 128) << 16));
        }
        gmaxs[tid] = g;
        cnt[tid] = 0;
    }
    __syncthreads();
    // Pass C: es per chunk, with early-out. es>0 <=> cmax >= gmax_j - 8.
    {
        int row = tid >> 4, seg = tid & 15;
        const int* srow = (const int*)&S[row * SW];
        int* urow = U + row * SCAN_P;
        #pragma unroll
        for (int cc = 0; cc < 8; cc++) {
            int j = cc * 16 + seg;
            unsigned pk = (unsigned)urow[j];
            int g = (int)(pk >> 24) - 128;
            int c = (int)((pk >> 16) & 0xFFu) - 128;
            if (c >= g - 8) {                      // relevant (es > 0); else es = 0 exactly
                int4 wv = *(const int4*)&srow[j * 4];
                int words[4] = {wv.x, wv.y, wv.z, wv.w};
                int es = 0;
                #pragma unroll
                for (int jw = 0; jw < 4; jw++) {
                    int wvv = words[jw];
                    #pragma unroll
                    for (int b = 0; b < 4; b++) {
                        int xv = (int)(int8_t)((unsigned)wvv >> (8 * b));
                        int df = g - xv;           // >= 0
                        es += (df < 9) ? (256 >> df) : 0;
                    }
                }
                urow[j] = (int)(pk | (unsigned)es);   // es <= 4096 fits 13 bits
                int pos = atomicAdd(&cnt[row], 1);
                lst[row * 128 + pos] = (unsigned char)j;
            }
        }
    }
    __syncthreads();
    // Pass D: exact sequential combine ps = (ps >> delta) + e
    if (tid < QROWS) {
        const int* urow = U + tid * SCAN_P;
        int ps = 0, gprev = -128;
        for (int j = 0; j < 128; j++) {
            unsigned pk = (unsigned)urow[j];
            int g = (int)(pk >> 24) - 128;
            int e = (int)(pk & 0x1FFFu);
            int sh = g - gprev;                   // >= 0
            ps = (sh < 31) ? (ps >> sh) : 0;
            ps += e;
            gprev = g;
        }
        invs[tid] = 65280 / ps;                   // exact == floor(65280.0/ps)
    }
    __syncthreads();

    // -------- Phase 3: EXACT SPARSE attn @ V --------
    // Warp handles 2 rows; lanes cover d (lane, lane+32). Skipped chunks are exact 0.
    {
        const int* Vg = (const int*)g_Vp + (size_t)bh * (SEQ/4) * HD;
        const int b_ = bh / NHEADS, h = bh % NHEADS;
        #pragma unroll
        for (int r = 0; r < 2; r++) {
            int row = warp * 2 + r;
            int n = cnt[row];
            int gm = gmaxs[row];
            unsigned inv = (unsigned)invs[row];
            int acc0 = 0, acc1 = 0;
            for (int ii = 0; ii < n; ii++) {
                int j = (int)lst[row * 128 + ii];                 // chunk id 0..127
                int4 lw = *(const int4*)&S[row * SW + j * 4];     // broadcast
                int lwa[4] = {lw.x, lw.y, lw.z, lw.w};
                #pragma unroll
                for (int kw = 0; kw < 4; kw++) {
                    unsigned xw = (unsigned)lwa[kw];
                    unsigned aw = 0;
                    #pragma unroll
                    for (int bb2 = 0; bb2 < 4; bb2++) {
                        int xv = (int)(int8_t)(xw >> (8 * bb2));
                        int df = gm - xv;
                        if (df > 31) df = 31;
                        aw |= (inv >> df) << (8 * bb2);
                    }
                    int base = (j * 4 + kw) * 64;                  // kword * HD
                    acc0 = dp4a_us(aw, Vg[base + lane],      acc0);
                    acc1 = dp4a_us(aw, Vg[base + 32 + lane], acc1);
                }
            }
            int q = q0 + row;
            int8_t* dst = g_ctx + ((size_t)(b_ * SEQ + q)) * DMODEL + h * HD;
            dst[lane]      = (int8_t)clamp_i8(acc0 >> 8);         // floor(acc/256)
            dst[32 + lane] = (int8_t)clamp_i8(acc1 >> 8);
        }
    }
}

// ---------------------------------------------------------------------------
// Kernel 3: out = requantize(ctx @ wo^T + bo, 256, 7), f32x2, double-buffered.
// ---------------------------------------------------------------------------
__global__ void __launch_bounds__(256, 2) out_kernel(
    const float* __restrict__ wo, const float* __restrict__ bo,
    float* __restrict__ out)
{
    __shared__ float cs[2][16][132];
    __shared__ float ws[2][16][132];

    const int m0 = blockIdx.x * 128;
    const int n0 = blockIdx.y * 128;
    const int tid = threadIdx.x, tx = tid & 15, ty = tid >> 4;
    const int r0s = tid >> 2;
    const int c4s = tid & 3;

    unsigned long long acc[4][8];
    #pragma unroll
    for (int i = 0; i < 4; i++)
        #pragma unroll
        for (int j = 0; j < 8; j++) acc[i][j] = 0ULL;

    int pc[2]; float4 pw[2];
    #pragma unroll
    for (int it = 0; it < 2; it++) {
        int row = r0s + it * 64;
        pc[it] = *(const int*)&g_ctx[(size_t)(m0 + row) * DMODEL + c4s * 4];
        pw[it] = *(const float4*)&wo[(size_t)(n0 + row) * DMODEL + c4s * 4];
    }
    #pragma unroll
    for (int it = 0; it < 2; it++) {
        int row = r0s + it * 64;
        #pragma unroll
        for (int e = 0; e < 4; e++)
            cs[0][c4s*4+e][row] = (float)(int8_t)((unsigned)pc[it] >> (8*e));
        ws[0][c4s*4+0][row] = pw[it].x; ws[0][c4s*4+1][row] = pw[it].y;
        ws[0][c4s*4+2][row] = pw[it].z; ws[0][c4s*4+3][row] = pw[it].w;
    }
    __syncthreads();

    for (int kc = 0; kc < 24; kc++) {
        const int cur = kc & 1;
        if (kc + 1 < 24) {
            int k0 = (kc + 1) * 16;
            #pragma unroll
            for (int it = 0; it < 2; it++) {
                int row = r0s + it * 64;
                pc[it] = *(const int*)&g_ctx[(size_t)(m0 + row) * DMODEL + k0 + c4s * 4];
                pw[it] = *(const float4*)&wo[(size_t)(n0 + row) * DMODEL + k0 + c4s * 4];
            }
        }
        #pragma unroll
        for (int kk = 0; kk < 16; kk++) {
            ulonglong2 a01 = *(ulonglong2*)&cs[cur][kk][ty * 8];
            ulonglong2 a23 = *(ulonglong2*)&cs[cur][kk][ty * 8 + 4];
            float4 bA = *(float4*)&ws[cur][kk][tx * 4];
            float4 bB = *(float4*)&ws[cur][kk][64 + tx * 4];
            unsigned long long a[4] = {a01.x, a01.y, a23.x, a23.y};
            unsigned long long bd[8];
            bd[0] = pack2(bA.x, bA.x); bd[1] = pack2(bA.y, bA.y);
            bd[2] = pack2(bA.z, bA.z); bd[3] = pack2(bA.w, bA.w);
            bd[4] = pack2(bB.x, bB.x); bd[5] = pack2(bB.y, bB.y);
            bd[6] = pack2(bB.z, bB.z); bd[7] = pack2(bB.w, bB.w);
            #pragma unroll
            for (int i = 0; i < 4; i++)
                #pragma unroll
                for (int j = 0; j < 8; j++)
                    ffma2(acc[i][j], a[i], bd[j]);
        }
        if (kc + 1 < 24) {
            const int nb = (kc + 1) & 1;
            #pragma unroll
            for (int it = 0; it < 2; it++) {
                int row = r0s + it * 64;
                #pragma unroll
                for (int e = 0; e < 4; e++)
                    cs[nb][c4s*4+e][row] = (float)(int8_t)((unsigned)pc[it] >> (8*e));
                ws[nb][c4s*4+0][row] = pw[it].x; ws[nb][c4s*4+1][row] = pw[it].y;
                ws[nb][c4s*4+2][row] = pw[it].z; ws[nb][c4s*4+3][row] = pw[it].w;
            }
        }
        __syncthreads();
    }

    float bb[8];
    #pragma unroll
    for (int e = 0; e < 4; e++) bb[e] = bo[n0 + tx * 4 + e];
    #pragma unroll
    for (int e = 4; e < 8; e++) bb[e] = bo[n0 + 64 + tx * 4 + (e - 4)];

    #pragma unroll
    for (int mp = 0; mp < 4; mp++) {
        #pragma unroll
        for (int par = 0; par < 2; par++) {
            int m = m0 + ty * 8 + mp * 2 + par;
            float vals[8];
            #pragma unroll
            for (int j = 0; j < 8; j++) {
                float lo, hi; unpack2(acc[mp][j], lo, hi);
                float v = (par == 0) ? lo : hi;
                float r = floorf(((v + bb[j]) * 256.0f) * (1.0f / 128.0f));
                vals[j] = fminf(fmaxf(r, -128.0f), 127.0f);
            }
            *(float4*)&out[(size_t)m * DMODEL + n0 + tx * 4] =
                make_float4(vals[0], vals[1], vals[2], vals[3]);
            *(float4*)&out[(size_t)m * DMODEL + n0 + 64 + tx * 4] =
                make_float4(vals[4], vals[5], vals[6], vals[7]);
        }
    }
}

// ---------------------------------------------------------------------------
extern "C" void kernel_launch(void* const* d_in, const int* in_sizes, int n_in,
                              void* d_out, int out_size)
{
    const float* x  = (const float*)d_in[0];
    const float* wq = (const float*)d_in[1];
    const float* bq = (const float*)d_in[2];
    const float* wk = (const float*)d_in[3];
    const float* bk = (const float*)d_in[4];
    const float* wv = (const float*)d_in[5];
    const float* bv = (const float*)d_in[6];
    const float* wo = (const float*)d_in[7];
    const float* bo = (const float*)d_in[8];
    float* out = (float*)d_out;

    cudaFuncSetAttribute(attn_fused, cudaFuncAttributeMaxDynamicSharedMemorySize,
                         ATTN_SMEM_BYTES);

    proj_kernel<<<dim3(64, 3, 3), 256>>>(x, wq, bq, wk, bk, wv, bv);
    attn_fused<<<dim3(128, 24), 256, ATTN_SMEM_BYTES>>>();
    out_kernel<<<dim3(64, 3), 256>>>(wo, bo, out);
}